// round 12
// baseline (speedup 1.0000x reference)
#include <cuda_runtime.h>
#include <cstdint>
#include <stdint.h>
#include <math.h>

#define S_LEN  2048
#define BATCH  2
#define DMODEL 1024
#define NH     16
#define HD     64

// Scratch (allocation-free requirement)
__device__ float g_qkv[BATCH * S_LEN * 3 * DMODEL];        // [b, s, 3d] (tf32-rounded)
__device__ float g_att[BATCH * S_LEN * DMODEL];            // features-rounded, then attn out
__device__ float g_w[4 * DMODEL * DMODEL];                 // rounded qkv_w | out_w

// ---------------------------------------------------------------------------
// helpers
// ---------------------------------------------------------------------------
__device__ __forceinline__ unsigned f2tf32(float f) {
    unsigned u;
    asm("cvt.rna.tf32.f32 %0, %1;" : "=r"(u) : "f"(f));
    return u;
}
__device__ __forceinline__ float tf32f(float f) {
    return __uint_as_float(f2tf32(f));
}
__device__ __forceinline__ void mma_tf32(float c[4], unsigned a0, unsigned a1,
                                         unsigned a2, unsigned a3,
                                         unsigned b0, unsigned b1) {
    asm("mma.sync.aligned.m16n8k8.row.col.f32.tf32.tf32.f32 "
        "{%0,%1,%2,%3}, {%4,%5,%6,%7}, {%8,%9}, {%0,%1,%2,%3};"
        : "+f"(c[0]), "+f"(c[1]), "+f"(c[2]), "+f"(c[3])
        : "r"(a0), "r"(a1), "r"(a2), "r"(a3), "r"(b0), "r"(b1));
}
__device__ __forceinline__ void ldsm_x4(unsigned& r0, unsigned& r1,
                                        unsigned& r2, unsigned& r3, unsigned addr) {
    asm volatile("ldmatrix.sync.aligned.m8n8.x4.shared.b16 {%0,%1,%2,%3}, [%4];"
                 : "=r"(r0), "=r"(r1), "=r"(r2), "=r"(r3) : "r"(addr));
}
__device__ __forceinline__ void ldsm_x2(unsigned& r0, unsigned& r1, unsigned addr) {
    asm volatile("ldmatrix.sync.aligned.m8n8.x2.shared.b16 {%0,%1}, [%2];"
                 : "=r"(r0), "=r"(r1) : "r"(addr));
}
__device__ __forceinline__ void cp_async16(unsigned int dst, const void* src) {
    asm volatile("cp.async.cg.shared.global [%0], [%1], 16;" :: "r"(dst), "l"(src));
}
__device__ __forceinline__ void cp_commit() {
    asm volatile("cp.async.commit_group;");
}
template<int N>
__device__ __forceinline__ void cp_wait() {
    asm volatile("cp.async.wait_group %0;" :: "n"(N));
}

// ---------------------------------------------------------------------------
// Fused elementwise tf32 rounding for features | qkv_w | out_w (idempotent)
// ---------------------------------------------------------------------------
#define NF4  (BATCH * S_LEN * DMODEL / 4)
#define NW14 (3 * DMODEL * DMODEL / 4)
#define NW24 (DMODEL * DMODEL / 4)

__global__ void round_all_kernel(const float4* __restrict__ f,
                                 const float4* __restrict__ w1,
                                 const float4* __restrict__ w2,
                                 float4* __restrict__ of,
                                 float4* __restrict__ ow1,
                                 float4* __restrict__ ow2)
{
    int i = blockIdx.x * blockDim.x + threadIdx.x;
    const float4* src; float4* dst; int j;
    if (i < NF4)                { src = f;  dst = of;  j = i; }
    else if (i < NF4 + NW14)    { src = w1; dst = ow1; j = i - NF4; }
    else if (i < NF4 + NW14 + NW24) { src = w2; dst = ow2; j = i - NF4 - NW14; }
    else return;
    float4 v = src[j];
    v.x = tf32f(v.x); v.y = tf32f(v.y);
    v.z = tf32f(v.z); v.w = tf32f(v.w);
    dst[j] = v;
}

// ---------------------------------------------------------------------------
// TF32 tensor-core GEMM: 512 threads (16 warps, 4M x 4N, 32x32 warp tile),
// 5-stage cp.async ring, ldmatrix fragment loads.
// C[M,N] = A[M,K]*B[N,K]^T + bias[N].  Inputs pre-rounded to tf32.
// ---------------------------------------------------------------------------
#define GSTG (128 * 36)
#define GSTAGE (2 * GSTG)
#define GSTAGES 5

template<int N_, int K_, bool ROUND>
__global__ __launch_bounds__(512, 1)
void gemm_tc(const float* __restrict__ A, const float* __restrict__ B,
             const float* __restrict__ bias, float* __restrict__ C)
{
    extern __shared__ float sm[];
    const unsigned int smAddr = (unsigned int)__cvta_generic_to_shared(sm);

    const int tid  = threadIdx.x;
    const int warp = tid >> 5;           // 0..15
    const int lane = tid & 31;
    const int gid  = lane >> 2;
    const int tig  = lane & 3;
    const int warpM = (warp & 3) * 32;   // 4 warps in M
    const int warpN = (warp >> 2) * 32;  // 4 warps in N
    const int mBase = blockIdx.y * 128;
    const int nBase = blockIdx.x * 128;

    // ldmatrix per-lane row addresses (byte offsets within a stage)
    const int lg = lane >> 3;            // matrix group 0..3
    const int lr = lane & 7;             // row within matrix
    const unsigned aLdsmBase =
        (unsigned)(((warpM + (lg & 1) * 8 + lr) * 36 + (lg >> 1) * 4) * 4);
    const unsigned bLdsmBase =
        (unsigned)(((warpN + lr) * 36 + (lg & 1) * 4) * 4);

    // stage loads: 1024 float4 slots per tile / 512 threads = 2 each
    int lrow[2], lcol[2];
    #pragma unroll
    for (int i = 0; i < 2; i++) {
        int s4 = tid + i * 512;
        lrow[i] = s4 >> 3;
        lcol[i] = (s4 & 7) * 4;
    }

    auto issue_stage = [&](int stage, int k0) {
        unsigned int aB = smAddr + stage * GSTAGE * 4;
        unsigned int bB = aB + GSTG * 4;
        #pragma unroll
        for (int i = 0; i < 2; i++) {
            unsigned int off = (lrow[i] * 36 + lcol[i]) * 4;
            cp_async16(aB + off, A + (size_t)(mBase + lrow[i]) * K_ + k0 + lcol[i]);
            cp_async16(bB + off, B + (size_t)(nBase + lrow[i]) * K_ + k0 + lcol[i]);
        }
    };

    float acc[8][4];                     // mt (2) x nt (4)
    #pragma unroll
    for (int i = 0; i < 8; i++)
        #pragma unroll
        for (int j = 0; j < 4; j++) acc[i][j] = 0.0f;

    const int kTiles = K_ / 32;
    #pragma unroll
    for (int s = 0; s < GSTAGES - 1; s++) {
        issue_stage(s, s * 32);
        cp_commit();
    }

    for (int kt = 0; kt < kTiles; kt++) {
        const int rem = kTiles - kt;     // in-flight groups = min(4, rem)
        if      (rem >= 4) cp_wait<3>();
        else if (rem == 3) cp_wait<2>();
        else if (rem == 2) cp_wait<1>();
        else               cp_wait<0>();
        __syncthreads();
        if (kt + GSTAGES - 1 < kTiles) {
            issue_stage((kt + GSTAGES - 1) % GSTAGES, (kt + GSTAGES - 1) * 32);
            cp_commit();
        }

        const unsigned stA = smAddr + (kt % GSTAGES) * (GSTAGE * 4);
        const unsigned stB = stA + GSTG * 4;

        #pragma unroll
        for (int ks = 0; ks < 4; ks++) {
            unsigned afr[2][4], bfr[4][2];
            #pragma unroll
            for (int mt = 0; mt < 2; mt++)
                ldsm_x4(afr[mt][0], afr[mt][1], afr[mt][2], afr[mt][3],
                        stA + aLdsmBase + (unsigned)((mt * 16 * 36 + ks * 8) * 4));
            #pragma unroll
            for (int nt = 0; nt < 4; nt++)
                ldsm_x2(bfr[nt][0], bfr[nt][1],
                        stB + bLdsmBase + (unsigned)((nt * 8 * 36 + ks * 8) * 4));
            #pragma unroll
            for (int mt = 0; mt < 2; mt++)
                #pragma unroll
                for (int nt = 0; nt < 4; nt++)
                    mma_tf32(acc[mt * 4 + nt], afr[mt][0], afr[mt][1],
                             afr[mt][2], afr[mt][3], bfr[nt][0], bfr[nt][1]);
        }
    }

    #pragma unroll
    for (int mt = 0; mt < 2; mt++) {
        #pragma unroll
        for (int nt = 0; nt < 4; nt++) {
            int row  = mBase + warpM + mt * 16 + gid;
            int coln = nBase + warpN + nt * 8 + 2 * tig;
            float b0 = bias[coln], b1 = bias[coln + 1];
            float* acc4 = acc[mt * 4 + nt];
            float2 w0, w1;
            if (ROUND) {
                w0.x = tf32f(acc4[0] + b0); w0.y = tf32f(acc4[1] + b1);
                w1.x = tf32f(acc4[2] + b0); w1.y = tf32f(acc4[3] + b1);
            } else {
                w0.x = acc4[0] + b0; w0.y = acc4[1] + b1;
                w1.x = acc4[2] + b0; w1.y = acc4[3] + b1;
            }
            *(float2*)(C + (size_t)row * N_ + coln)       = w0;
            *(float2*)(C + (size_t)(row + 8) * N_ + coln) = w1;
        }
    }
}

// ---------------------------------------------------------------------------
// TF32 flash attention (unchanged from R11): ldmatrix Q/K, LDS.32 V,
// folded 1/8 scale, double-buffered cp.async K/V, 2 CTAs/SM.
// ---------------------------------------------------------------------------
#define QLD 68
#define KLD 68
#define VLD 72
#define Q_FLOATS (128 * QLD)
#define K_FLOATS (64 * KLD)
#define V_FLOATS (64 * VLD)

__global__ __launch_bounds__(256, 2)
void flash_attn_tc(const float* __restrict__ qkv, float* __restrict__ out,
                   const int* __restrict__ causal_flag)
{
    extern __shared__ float sm[];
    float* Qs = sm;
    float* Kbuf = Qs + Q_FLOATS;
    float* Vbuf = Kbuf + 2 * K_FLOATS;
    const unsigned int smAddr = (unsigned int)__cvta_generic_to_shared(sm);
    const unsigned int kAddr0 = smAddr + Q_FLOATS * 4;
    const unsigned int vAddr0 = kAddr0 + 2 * K_FLOATS * 4;

    const int tid  = threadIdx.x;
    const int warp = tid >> 5;
    const int lane = tid & 31;
    const int gid  = lane >> 2;
    const int tig  = lane & 3;
    const int qBase = blockIdx.x * 128;
    const int h = blockIdx.y;
    const int b = blockIdx.z;
    const bool causal = (*causal_flag != 0);

    const int rowStride = 3 * DMODEL;
    const float* qp = qkv + (size_t)b * S_LEN * rowStride + h * HD;
    const float* kp = qp + DMODEL;
    const float* vp = qp + 2 * DMODEL;

    const int lg = lane >> 3;
    const int lr = lane & 7;
    const unsigned qLdsmBase = smAddr +
        (unsigned)(((warp * 16 + (lg & 1) * 8 + lr) * QLD + (lg >> 1) * 4) * 4);
    const unsigned kLdsmBase =
        (unsigned)((lr * KLD + (lg & 1) * 4) * 4);

    int kn[4], kc[4];
    #pragma unroll
    for (int i = 0; i < 4; i++) {
        int s4 = tid + i * 256;
        kn[i] = s4 >> 4;
        kc[i] = (s4 & 15) * 4;
    }
    auto issue_kv = [&](int buf, int kBase) {
        unsigned int kB = kAddr0 + buf * K_FLOATS * 4;
        unsigned int vB = vAddr0 + buf * V_FLOATS * 4;
        #pragma unroll
        for (int i = 0; i < 4; i++) {
            size_t g = (size_t)(kBase + kn[i]) * rowStride + kc[i];
            cp_async16(kB + (kn[i] * KLD + kc[i]) * 4, kp + g);
            cp_async16(vB + (kn[i] * VLD + kc[i]) * 4, vp + g);
        }
    };

    int nTiles = S_LEN / 64;
    if (causal) nTiles = (qBase + 128) / 64;

    issue_kv(0, 0);
    cp_commit();

    // Q load with folded 1/8 scale (exact on tf32 values)
    #pragma unroll
    for (int i = 0; i < 8; i++) {
        int s4 = tid + i * 256;
        int m  = s4 >> 4;
        int c  = (s4 & 15) * 4;
        float4 v = *(const float4*)(qp + (size_t)(qBase + m) * rowStride + c);
        v.x *= 0.125f; v.y *= 0.125f; v.z *= 0.125f; v.w *= 0.125f;
        *(float4*)&Qs[m * QLD + c] = v;
    }

    float of[8][4];
    #pragma unroll
    for (int i = 0; i < 8; i++)
        #pragma unroll
        for (int j = 0; j < 4; j++) of[i][j] = 0.0f;
    float mrow0 = -1e30f, mrow1 = -1e30f, lrow0 = 0.0f, lrow1 = 0.0f;

    const int row0g = qBase + warp * 16 + gid;

    for (int t = 0; t < nTiles; t++) {
        const int kBase = t * 64;
        const int buf   = t & 1;

        cp_wait<0>();
        __syncthreads();
        if (t + 1 < nTiles) {
            issue_kv(1 - buf, kBase + 64);
            cp_commit();
        }

        const unsigned kStage = kAddr0 + buf * K_FLOATS * 4;
        const float* Vs = Vbuf + buf * V_FLOATS;

        float sc[8][4];
        #pragma unroll
        for (int i = 0; i < 8; i++)
            #pragma unroll
            for (int j = 0; j < 4; j++) sc[i][j] = 0.0f;

        #pragma unroll
        for (int ks = 0; ks < 8; ks++) {
            unsigned a0, a1, a2, a3;
            ldsm_x4(a0, a1, a2, a3, qLdsmBase + (unsigned)(ks * 32));
            #pragma unroll
            for (int nt = 0; nt < 8; nt++) {
                unsigned b0, b1;
                ldsm_x2(b0, b1,
                        kStage + kLdsmBase + (unsigned)((nt * 8 * KLD + ks * 8) * 4));
                mma_tf32(sc[nt], a0, a1, a2, a3, b0, b1);
            }
        }

        float ml0 = -1e30f, ml1 = -1e30f;
        #pragma unroll
        for (int nt = 0; nt < 8; nt++) {
            int coln = kBase + nt * 8 + 2 * tig;
            #pragma unroll
            for (int cc = 0; cc < 4; cc++) {
                float v = sc[nt][cc];
                if (causal) {
                    int col = coln + (cc & 1);
                    int row = (cc < 2) ? row0g : (row0g + 8);
                    if (col > row) v = -1e30f;
                }
                sc[nt][cc] = v;
                if (cc < 2) ml0 = fmaxf(ml0, v);
                else        ml1 = fmaxf(ml1, v);
            }
        }
        #pragma unroll
        for (int off = 1; off < 4; off <<= 1) {
            ml0 = fmaxf(ml0, __shfl_xor_sync(0xffffffffu, ml0, off));
            ml1 = fmaxf(ml1, __shfl_xor_sync(0xffffffffu, ml1, off));
        }
        float mn0 = fmaxf(mrow0, ml0), mn1 = fmaxf(mrow1, ml1);
        float al0 = __expf(mrow0 - mn0), al1 = __expf(mrow1 - mn1);
        mrow0 = mn0; mrow1 = mn1;

        float rs0 = 0.0f, rs1 = 0.0f;
        #pragma unroll
        for (int nt = 0; nt < 8; nt++) {
            float p0 = __expf(sc[nt][0] - mn0);
            float p1 = __expf(sc[nt][1] - mn0);
            float p2 = __expf(sc[nt][2] - mn1);
            float p3 = __expf(sc[nt][3] - mn1);
            sc[nt][0] = p0; sc[nt][1] = p1; sc[nt][2] = p2; sc[nt][3] = p3;
            rs0 += p0 + p1; rs1 += p2 + p3;
        }
        #pragma unroll
        for (int off = 1; off < 4; off <<= 1) {
            rs0 += __shfl_xor_sync(0xffffffffu, rs0, off);
            rs1 += __shfl_xor_sync(0xffffffffu, rs1, off);
        }
        lrow0 = lrow0 * al0 + rs0;
        lrow1 = lrow1 * al1 + rs1;
        #pragma unroll
        for (int dt = 0; dt < 8; dt++) {
            of[dt][0] *= al0; of[dt][1] *= al0;
            of[dt][2] *= al1; of[dt][3] *= al1;
        }

        const int l0 = (lane & 28) | (tig >> 1);
        const int l1 = l0 + 2;
        const bool odd = (tig & 1);
        #pragma unroll
        for (int kt = 0; kt < 8; kt++) {
            float p00 = __shfl_sync(0xffffffffu, sc[kt][0], l0);
            float p01 = __shfl_sync(0xffffffffu, sc[kt][1], l0);
            float p10 = __shfl_sync(0xffffffffu, sc[kt][2], l0);
            float p11 = __shfl_sync(0xffffffffu, sc[kt][3], l0);
            float q00 = __shfl_sync(0xffffffffu, sc[kt][0], l1);
            float q01 = __shfl_sync(0xffffffffu, sc[kt][1], l1);
            float q10 = __shfl_sync(0xffffffffu, sc[kt][2], l1);
            float q11 = __shfl_sync(0xffffffffu, sc[kt][3], l1);
            unsigned a0 = f2tf32(odd ? p01 : p00);
            unsigned a1 = f2tf32(odd ? p11 : p10);
            unsigned a2 = f2tf32(odd ? q01 : q00);
            unsigned a3 = f2tf32(odd ? q11 : q10);
            #pragma unroll
            for (int dt = 0; dt < 8; dt++) {
                unsigned b0 = __float_as_uint(Vs[(kt * 8 + tig) * VLD + dt * 8 + gid]);
                unsigned b1 = __float_as_uint(Vs[(kt * 8 + tig + 4) * VLD + dt * 8 + gid]);
                mma_tf32(of[dt], a0, a1, a2, a3, b0, b1);
            }
        }
    }

    float inv0 = 1.0f / lrow0, inv1 = 1.0f / lrow1;
    float* op = out + (size_t)b * S_LEN * DMODEL + h * HD;
    #pragma unroll
    for (int dt = 0; dt < 8; dt++) {
        int col = dt * 8 + 2 * tig;
        float2 w0, w1;
        w0.x = tf32f(of[dt][0] * inv0); w0.y = tf32f(of[dt][1] * inv0);
        w1.x = tf32f(of[dt][2] * inv1); w1.y = tf32f(of[dt][3] * inv1);
        *(float2*)(op + (size_t)row0g * DMODEL + col)       = w0;
        *(float2*)(op + (size_t)(row0g + 8) * DMODEL + col) = w1;
    }
}

// ---------------------------------------------------------------------------
extern "C" void kernel_launch(void* const* d_in, const int* in_sizes, int n_in,
                              void* d_out, int out_size)
{
    (void)in_sizes; (void)n_in; (void)out_size;
    const float* features = (const float*)d_in[0];
    const float* qkv_w    = (const float*)d_in[1];
    const float* qkv_b    = (const float*)d_in[2];
    const float* out_w    = (const float*)d_in[3];
    const float* out_b    = (const float*)d_in[4];
    const int*   causal   = (const int*)d_in[5];
    float* out = (float*)d_out;

    float* qkvbuf = nullptr;
    float* attbuf = nullptr;
    float* wbuf   = nullptr;
    cudaGetSymbolAddress((void**)&qkvbuf, g_qkv);
    cudaGetSymbolAddress((void**)&attbuf, g_att);
    cudaGetSymbolAddress((void**)&wbuf,   g_w);

    const int SMEM_GEMM  = GSTAGES * GSTAGE * (int)sizeof(float);   // 184320
    const int SMEM_FLASH = (Q_FLOATS + 2 * K_FLOATS + 2 * V_FLOATS)
                           * (int)sizeof(float);                     // 106496

    cudaFuncSetAttribute(gemm_tc<3 * DMODEL, DMODEL, true>,
                         cudaFuncAttributeMaxDynamicSharedMemorySize, SMEM_GEMM);
    cudaFuncSetAttribute(gemm_tc<DMODEL, DMODEL, false>,
                         cudaFuncAttributeMaxDynamicSharedMemorySize, SMEM_GEMM);
    cudaFuncSetAttribute(flash_attn_tc,
                         cudaFuncAttributeMaxDynamicSharedMemorySize, SMEM_FLASH);

    // 0) fused pre-rounding of all inputs to tf32 values
    {
        int total4 = NF4 + NW14 + NW24;
        round_all_kernel<<<(total4 + 255) / 256, 256>>>(
            (const float4*)features, (const float4*)qkv_w, (const float4*)out_w,
            (float4*)attbuf, (float4*)wbuf,
            (float4*)(wbuf + 3 * DMODEL * DMODEL));
    }

    // 1) QKV projection (rounded output feeds attention)
    gemm_tc<3 * DMODEL, DMODEL, true>
        <<<dim3(3 * DMODEL / 128, BATCH * S_LEN / 128), 512, SMEM_GEMM>>>(
            attbuf, wbuf, qkv_b, qkvbuf);

    // 2) Attention (reads rounded qkv, writes rounded output over g_att)
    flash_attn_tc<<<dim3(S_LEN / 128, NH, BATCH), 256, SMEM_FLASH>>>(
        qkvbuf, attbuf, causal);

    // 3) Output projection (exact fp32 output)
    gemm_tc<DMODEL, DMODEL, false>
        <<<dim3(DMODEL / 128, BATCH * S_LEN / 128), 512, SMEM_GEMM>>>(
            attbuf, wbuf + 3 * DMODEL * DMODEL, out_b, out);
}

// round 13
// speedup vs baseline: 1.1815x; 1.1815x over previous
#include <cuda_runtime.h>
#include <cstdint>
#include <stdint.h>
#include <math.h>

#define S_LEN  2048
#define BATCH  2
#define DMODEL 1024
#define NH     16
#define HD     64

// Scratch (allocation-free requirement)
__device__ float g_qkv[BATCH * S_LEN * 3 * DMODEL];        // [b, s, 3d] (tf32-rounded)
__device__ float g_att[BATCH * S_LEN * DMODEL];            // features-rounded, then attn out
__device__ float g_w[4 * DMODEL * DMODEL];                 // rounded qkv_w | out_w

// ---------------------------------------------------------------------------
// helpers
// ---------------------------------------------------------------------------
__device__ __forceinline__ unsigned f2tf32(float f) {
    unsigned u;
    asm("cvt.rna.tf32.f32 %0, %1;" : "=r"(u) : "f"(f));
    return u;
}
__device__ __forceinline__ float tf32f(float f) {
    return __uint_as_float(f2tf32(f));
}
__device__ __forceinline__ void mma_tf32(float c[4], unsigned a0, unsigned a1,
                                         unsigned a2, unsigned a3,
                                         unsigned b0, unsigned b1) {
    asm("mma.sync.aligned.m16n8k8.row.col.f32.tf32.tf32.f32 "
        "{%0,%1,%2,%3}, {%4,%5,%6,%7}, {%8,%9}, {%0,%1,%2,%3};"
        : "+f"(c[0]), "+f"(c[1]), "+f"(c[2]), "+f"(c[3])
        : "r"(a0), "r"(a1), "r"(a2), "r"(a3), "r"(b0), "r"(b1));
}
__device__ __forceinline__ void ldsm_x4(unsigned& r0, unsigned& r1,
                                        unsigned& r2, unsigned& r3, unsigned addr) {
    asm volatile("ldmatrix.sync.aligned.m8n8.x4.shared.b16 {%0,%1,%2,%3}, [%4];"
                 : "=r"(r0), "=r"(r1), "=r"(r2), "=r"(r3) : "r"(addr));
}
__device__ __forceinline__ void cp_async16(unsigned int dst, const void* src) {
    asm volatile("cp.async.cg.shared.global [%0], [%1], 16;" :: "r"(dst), "l"(src));
}
__device__ __forceinline__ void cp_commit() {
    asm volatile("cp.async.commit_group;");
}
template<int N>
__device__ __forceinline__ void cp_wait() {
    asm volatile("cp.async.wait_group %0;" :: "n"(N));
}

// ---------------------------------------------------------------------------
// Fused elementwise tf32 rounding for features | qkv_w | out_w (idempotent)
// ---------------------------------------------------------------------------
#define NF4  (BATCH * S_LEN * DMODEL / 4)
#define NW14 (3 * DMODEL * DMODEL / 4)
#define NW24 (DMODEL * DMODEL / 4)

__global__ void round_all_kernel(const float4* __restrict__ f,
                                 const float4* __restrict__ w1,
                                 const float4* __restrict__ w2,
                                 float4* __restrict__ of,
                                 float4* __restrict__ ow1,
                                 float4* __restrict__ ow2)
{
    int i = blockIdx.x * blockDim.x + threadIdx.x;
    const float4* src; float4* dst; int j;
    if (i < NF4)                { src = f;  dst = of;  j = i; }
    else if (i < NF4 + NW14)    { src = w1; dst = ow1; j = i - NF4; }
    else if (i < NF4 + NW14 + NW24) { src = w2; dst = ow2; j = i - NF4 - NW14; }
    else return;
    float4 v = src[j];
    v.x = tf32f(v.x); v.y = tf32f(v.y);
    v.z = tf32f(v.z); v.w = tf32f(v.w);
    dst[j] = v;
}

// ---------------------------------------------------------------------------
// TF32 tensor-core GEMM (R11 shape): 256 thr, 8 warps (2M x 4N, 64x32 tile),
// 3-stage cp.async ring, packed-x4 ldmatrix for A and B-pairs.
// C[M,N] = A[M,K]*B[N,K]^T + bias[N].  Inputs pre-rounded to tf32.
// ---------------------------------------------------------------------------
#define GSTG (128 * 36)
#define GSTAGE (2 * GSTG)
#define GSTAGES 3

template<int N_, int K_, bool ROUND>
__global__ __launch_bounds__(256, 2)
void gemm_tc(const float* __restrict__ A, const float* __restrict__ B,
             const float* __restrict__ bias, float* __restrict__ C)
{
    extern __shared__ float sm[];
    const unsigned int smAddr = (unsigned int)__cvta_generic_to_shared(sm);

    const int tid  = threadIdx.x;
    const int warp = tid >> 5;
    const int lane = tid & 31;
    const int gid  = lane >> 2;
    const int tig  = lane & 3;
    const int warpM = (warp & 1) * 64;
    const int warpN = (warp >> 1) * 32;
    const int mBase = blockIdx.y * 128;
    const int nBase = blockIdx.x * 128;

    const int lg = lane >> 3;            // matrix group 0..3
    const int lr = lane & 7;             // row within matrix
    // A x4: m0=(rows m..m+8, k0-4) m1=(rows m+8..m+16, k0-4) m2,m3 = same rows k4-8
    const unsigned aLdsmBase =
        (unsigned)(((warpM + (lg & 1) * 8 + lr) * 36 + (lg >> 1) * 4) * 4);
    // B pair x4: m0=(nt rows, k0-4) m1=(nt rows, k4-8) m2,m3 = nt+1 rows
    const unsigned bPairBase =
        (unsigned)(((warpN + (lg >> 1) * 8 + lr) * 36 + (lg & 1) * 4) * 4);

    int lrow[4], lcol[4];
    #pragma unroll
    for (int i = 0; i < 4; i++) {
        int s4 = tid + i * 256;
        lrow[i] = s4 >> 3;
        lcol[i] = (s4 & 7) * 4;
    }

    auto issue_stage = [&](int stage, int k0) {
        unsigned int aB = smAddr + stage * GSTAGE * 4;
        unsigned int bB = aB + GSTG * 4;
        #pragma unroll
        for (int i = 0; i < 4; i++) {
            unsigned int off = (lrow[i] * 36 + lcol[i]) * 4;
            cp_async16(aB + off, A + (size_t)(mBase + lrow[i]) * K_ + k0 + lcol[i]);
            cp_async16(bB + off, B + (size_t)(nBase + lrow[i]) * K_ + k0 + lcol[i]);
        }
    };

    float acc[16][4];
    #pragma unroll
    for (int i = 0; i < 16; i++)
        #pragma unroll
        for (int j = 0; j < 4; j++) acc[i][j] = 0.0f;

    const int kTiles = K_ / 32;
    #pragma unroll
    for (int s = 0; s < GSTAGES - 1; s++) {
        issue_stage(s, s * 32);
        cp_commit();
    }

    for (int kt = 0; kt < kTiles; kt++) {
        if (kt == kTiles - 1) cp_wait<0>();
        else                  cp_wait<GSTAGES - 2>();
        __syncthreads();
        if (kt + GSTAGES - 1 < kTiles) {
            issue_stage((kt + GSTAGES - 1) % GSTAGES, (kt + GSTAGES - 1) * 32);
            cp_commit();
        }

        const unsigned stA = smAddr + (kt % GSTAGES) * (GSTAGE * 4);
        const unsigned stB = stA + GSTG * 4;

        #pragma unroll
        for (int ks = 0; ks < 4; ks++) {
            unsigned afr[4][4];
            #pragma unroll
            for (int mt = 0; mt < 4; mt++)
                ldsm_x4(afr[mt][0], afr[mt][1], afr[mt][2], afr[mt][3],
                        stA + aLdsmBase + (unsigned)((mt * 16 * 36 + ks * 8) * 4));
            #pragma unroll
            for (int p = 0; p < 2; p++) {
                unsigned b00, b01, b10, b11;
                ldsm_x4(b00, b01, b10, b11,
                        stB + bPairBase + (unsigned)((p * 16 * 36 + ks * 8) * 4));
                #pragma unroll
                for (int mt = 0; mt < 4; mt++) {
                    mma_tf32(acc[mt * 4 + 2 * p], afr[mt][0], afr[mt][1],
                             afr[mt][2], afr[mt][3], b00, b01);
                    mma_tf32(acc[mt * 4 + 2 * p + 1], afr[mt][0], afr[mt][1],
                             afr[mt][2], afr[mt][3], b10, b11);
                }
            }
        }
    }

    #pragma unroll
    for (int mt = 0; mt < 4; mt++) {
        #pragma unroll
        for (int nt = 0; nt < 4; nt++) {
            int row  = mBase + warpM + mt * 16 + gid;
            int coln = nBase + warpN + nt * 8 + 2 * tig;
            float b0 = bias[coln], b1 = bias[coln + 1];
            float* acc4 = acc[mt * 4 + nt];
            float2 w0, w1;
            if (ROUND) {
                w0.x = tf32f(acc4[0] + b0); w0.y = tf32f(acc4[1] + b1);
                w1.x = tf32f(acc4[2] + b0); w1.y = tf32f(acc4[3] + b1);
            } else {
                w0.x = acc4[0] + b0; w0.y = acc4[1] + b1;
                w1.x = acc4[2] + b0; w1.y = acc4[3] + b1;
            }
            *(float2*)(C + (size_t)row * N_ + coln)       = w0;
            *(float2*)(C + (size_t)(row + 8) * N_ + coln) = w1;
        }
    }
}

// ---------------------------------------------------------------------------
// TF32 flash attention (R11 base): ldmatrix Q x4, K via packed-pair x4,
// LDS.32 V, folded 1/8 scale, double-buffered cp.async K/V, 2 CTAs/SM.
// ---------------------------------------------------------------------------
#define QLD 68
#define KLD 68
#define VLD 72
#define Q_FLOATS (128 * QLD)
#define K_FLOATS (64 * KLD)
#define V_FLOATS (64 * VLD)

__global__ __launch_bounds__(256, 2)
void flash_attn_tc(const float* __restrict__ qkv, float* __restrict__ out,
                   const int* __restrict__ causal_flag)
{
    extern __shared__ float sm[];
    float* Qs = sm;
    float* Kbuf = Qs + Q_FLOATS;
    float* Vbuf = Kbuf + 2 * K_FLOATS;
    const unsigned int smAddr = (unsigned int)__cvta_generic_to_shared(sm);
    const unsigned int kAddr0 = smAddr + Q_FLOATS * 4;
    const unsigned int vAddr0 = kAddr0 + 2 * K_FLOATS * 4;

    const int tid  = threadIdx.x;
    const int warp = tid >> 5;
    const int lane = tid & 31;
    const int gid  = lane >> 2;
    const int tig  = lane & 3;
    const int qBase = blockIdx.x * 128;
    const int h = blockIdx.y;
    const int b = blockIdx.z;
    const bool causal = (*causal_flag != 0);

    const int rowStride = 3 * DMODEL;
    const float* qp = qkv + (size_t)b * S_LEN * rowStride + h * HD;
    const float* kp = qp + DMODEL;
    const float* vp = qp + 2 * DMODEL;

    const int lg = lane >> 3;
    const int lr = lane & 7;
    const unsigned qLdsmBase = smAddr +
        (unsigned)(((warp * 16 + (lg & 1) * 8 + lr) * QLD + (lg >> 1) * 4) * 4);
    // K pair x4: m0=(nt rows,k0-4) m1=(nt,k4-8) m2,m3 = nt+1 rows
    const unsigned kPairBase =
        (unsigned)((((lg >> 1) * 8 + lr) * KLD + (lg & 1) * 4) * 4);

    int kn[4], kc[4];
    #pragma unroll
    for (int i = 0; i < 4; i++) {
        int s4 = tid + i * 256;
        kn[i] = s4 >> 4;
        kc[i] = (s4 & 15) * 4;
    }
    auto issue_kv = [&](int buf, int kBase) {
        unsigned int kB = kAddr0 + buf * K_FLOATS * 4;
        unsigned int vB = vAddr0 + buf * V_FLOATS * 4;
        #pragma unroll
        for (int i = 0; i < 4; i++) {
            size_t g = (size_t)(kBase + kn[i]) * rowStride + kc[i];
            cp_async16(kB + (kn[i] * KLD + kc[i]) * 4, kp + g);
            cp_async16(vB + (kn[i] * VLD + kc[i]) * 4, vp + g);
        }
    };

    int nTiles = S_LEN / 64;
    if (causal) nTiles = (qBase + 128) / 64;

    issue_kv(0, 0);
    cp_commit();

    // Q load with folded 1/8 scale (exact on tf32 values)
    #pragma unroll
    for (int i = 0; i < 8; i++) {
        int s4 = tid + i * 256;
        int m  = s4 >> 4;
        int c  = (s4 & 15) * 4;
        float4 v = *(const float4*)(qp + (size_t)(qBase + m) * rowStride + c);
        v.x *= 0.125f; v.y *= 0.125f; v.z *= 0.125f; v.w *= 0.125f;
        *(float4*)&Qs[m * QLD + c] = v;
    }

    float of[8][4];
    #pragma unroll
    for (int i = 0; i < 8; i++)
        #pragma unroll
        for (int j = 0; j < 4; j++) of[i][j] = 0.0f;
    float mrow0 = -1e30f, mrow1 = -1e30f, lrow0 = 0.0f, lrow1 = 0.0f;

    const int row0g = qBase + warp * 16 + gid;

    for (int t = 0; t < nTiles; t++) {
        const int kBase = t * 64;
        const int buf   = t & 1;

        cp_wait<0>();
        __syncthreads();
        if (t + 1 < nTiles) {
            issue_kv(1 - buf, kBase + 64);
            cp_commit();
        }

        const unsigned kStage = kAddr0 + buf * K_FLOATS * 4;
        const float* Vs = Vbuf + buf * V_FLOATS;

        // ---- Phase A: S = (Q/8) K^T (packed K fragment pairs) ----
        float sc[8][4];
        #pragma unroll
        for (int i = 0; i < 8; i++)
            #pragma unroll
            for (int j = 0; j < 4; j++) sc[i][j] = 0.0f;

        #pragma unroll
        for (int ks = 0; ks < 8; ks++) {
            unsigned a0, a1, a2, a3;
            ldsm_x4(a0, a1, a2, a3, qLdsmBase + (unsigned)(ks * 32));
            #pragma unroll
            for (int p = 0; p < 4; p++) {
                unsigned b00, b01, b10, b11;
                ldsm_x4(b00, b01, b10, b11,
                        kStage + kPairBase + (unsigned)((p * 16 * KLD + ks * 8) * 4));
                mma_tf32(sc[2 * p],     a0, a1, a2, a3, b00, b01);
                mma_tf32(sc[2 * p + 1], a0, a1, a2, a3, b10, b11);
            }
        }

        // ---- online softmax (values already scaled) ----
        float ml0 = -1e30f, ml1 = -1e30f;
        #pragma unroll
        for (int nt = 0; nt < 8; nt++) {
            int coln = kBase + nt * 8 + 2 * tig;
            #pragma unroll
            for (int cc = 0; cc < 4; cc++) {
                float v = sc[nt][cc];
                if (causal) {
                    int col = coln + (cc & 1);
                    int row = (cc < 2) ? row0g : (row0g + 8);
                    if (col > row) v = -1e30f;
                }
                sc[nt][cc] = v;
                if (cc < 2) ml0 = fmaxf(ml0, v);
                else        ml1 = fmaxf(ml1, v);
            }
        }
        #pragma unroll
        for (int off = 1; off < 4; off <<= 1) {
            ml0 = fmaxf(ml0, __shfl_xor_sync(0xffffffffu, ml0, off));
            ml1 = fmaxf(ml1, __shfl_xor_sync(0xffffffffu, ml1, off));
        }
        float mn0 = fmaxf(mrow0, ml0), mn1 = fmaxf(mrow1, ml1);
        float al0 = __expf(mrow0 - mn0), al1 = __expf(mrow1 - mn1);
        mrow0 = mn0; mrow1 = mn1;

        float rs0 = 0.0f, rs1 = 0.0f;
        #pragma unroll
        for (int nt = 0; nt < 8; nt++) {
            float p0 = __expf(sc[nt][0] - mn0);
            float p1 = __expf(sc[nt][1] - mn0);
            float p2 = __expf(sc[nt][2] - mn1);
            float p3 = __expf(sc[nt][3] - mn1);
            sc[nt][0] = p0; sc[nt][1] = p1; sc[nt][2] = p2; sc[nt][3] = p3;
            rs0 += p0 + p1; rs1 += p2 + p3;
        }
        #pragma unroll
        for (int off = 1; off < 4; off <<= 1) {
            rs0 += __shfl_xor_sync(0xffffffffu, rs0, off);
            rs1 += __shfl_xor_sync(0xffffffffu, rs1, off);
        }
        lrow0 = lrow0 * al0 + rs0;
        lrow1 = lrow1 * al1 + rs1;
        #pragma unroll
        for (int dt = 0; dt < 8; dt++) {
            of[dt][0] *= al0; of[dt][1] *= al0;
            of[dt][2] *= al1; of[dt][3] *= al1;
        }

        // ---- Phase B: O += P V (P via shuffles, V via LDS.32) ----
        const int l0 = (lane & 28) | (tig >> 1);
        const int l1 = l0 + 2;
        const bool odd = (tig & 1);
        #pragma unroll
        for (int kt = 0; kt < 8; kt++) {
            float p00 = __shfl_sync(0xffffffffu, sc[kt][0], l0);
            float p01 = __shfl_sync(0xffffffffu, sc[kt][1], l0);
            float p10 = __shfl_sync(0xffffffffu, sc[kt][2], l0);
            float p11 = __shfl_sync(0xffffffffu, sc[kt][3], l0);
            float q00 = __shfl_sync(0xffffffffu, sc[kt][0], l1);
            float q01 = __shfl_sync(0xffffffffu, sc[kt][1], l1);
            float q10 = __shfl_sync(0xffffffffu, sc[kt][2], l1);
            float q11 = __shfl_sync(0xffffffffu, sc[kt][3], l1);
            unsigned a0 = f2tf32(odd ? p01 : p00);
            unsigned a1 = f2tf32(odd ? p11 : p10);
            unsigned a2 = f2tf32(odd ? q01 : q00);
            unsigned a3 = f2tf32(odd ? q11 : q10);
            #pragma unroll
            for (int dt = 0; dt < 8; dt++) {
                unsigned b0 = __float_as_uint(Vs[(kt * 8 + tig) * VLD + dt * 8 + gid]);
                unsigned b1 = __float_as_uint(Vs[(kt * 8 + tig + 4) * VLD + dt * 8 + gid]);
                mma_tf32(of[dt], a0, a1, a2, a3, b0, b1);
            }
        }
    }

    // Epilogue: normalize, round to tf32 (gemm2 consumes without cvt)
    float inv0 = 1.0f / lrow0, inv1 = 1.0f / lrow1;
    float* op = out + (size_t)b * S_LEN * DMODEL + h * HD;
    #pragma unroll
    for (int dt = 0; dt < 8; dt++) {
        int col = dt * 8 + 2 * tig;
        float2 w0, w1;
        w0.x = tf32f(of[dt][0] * inv0); w0.y = tf32f(of[dt][1] * inv0);
        w1.x = tf32f(of[dt][2] * inv1); w1.y = tf32f(of[dt][3] * inv1);
        *(float2*)(op + (size_t)row0g * DMODEL + col)       = w0;
        *(float2*)(op + (size_t)(row0g + 8) * DMODEL + col) = w1;
    }
}

// ---------------------------------------------------------------------------
extern "C" void kernel_launch(void* const* d_in, const int* in_sizes, int n_in,
                              void* d_out, int out_size)
{
    (void)in_sizes; (void)n_in; (void)out_size;
    const float* features = (const float*)d_in[0];
    const float* qkv_w    = (const float*)d_in[1];
    const float* qkv_b    = (const float*)d_in[2];
    const float* out_w    = (const float*)d_in[3];
    const float* out_b    = (const float*)d_in[4];
    const int*   causal   = (const int*)d_in[5];
    float* out = (float*)d_out;

    float* qkvbuf = nullptr;
    float* attbuf = nullptr;
    float* wbuf   = nullptr;
    cudaGetSymbolAddress((void**)&qkvbuf, g_qkv);
    cudaGetSymbolAddress((void**)&attbuf, g_att);
    cudaGetSymbolAddress((void**)&wbuf,   g_w);

    const int SMEM_GEMM  = GSTAGES * GSTAGE * (int)sizeof(float);   // 110592
    const int SMEM_FLASH = (Q_FLOATS + 2 * K_FLOATS + 2 * V_FLOATS)
                           * (int)sizeof(float);                     // 106496

    cudaFuncSetAttribute(gemm_tc<3 * DMODEL, DMODEL, true>,
                         cudaFuncAttributeMaxDynamicSharedMemorySize, SMEM_GEMM);
    cudaFuncSetAttribute(gemm_tc<DMODEL, DMODEL, false>,
                         cudaFuncAttributeMaxDynamicSharedMemorySize, SMEM_GEMM);
    cudaFuncSetAttribute(flash_attn_tc,
                         cudaFuncAttributeMaxDynamicSharedMemorySize, SMEM_FLASH);

    // 0) fused pre-rounding of all inputs to tf32 values
    {
        int total4 = NF4 + NW14 + NW24;
        round_all_kernel<<<(total4 + 255) / 256, 256>>>(
            (const float4*)features, (const float4*)qkv_w, (const float4*)out_w,
            (float4*)attbuf, (float4*)wbuf,
            (float4*)(wbuf + 3 * DMODEL * DMODEL));
    }

    // 1) QKV projection (rounded output feeds attention)
    gemm_tc<3 * DMODEL, DMODEL, true>
        <<<dim3(3 * DMODEL / 128, BATCH * S_LEN / 128), 256, SMEM_GEMM>>>(
            attbuf, wbuf, qkv_b, qkvbuf);

    // 2) Attention (reads rounded qkv, writes rounded output over g_att)
    flash_attn_tc<<<dim3(S_LEN / 128, NH, BATCH), 256, SMEM_FLASH>>>(
        qkvbuf, attbuf, causal);

    // 3) Output projection (exact fp32 output)
    gemm_tc<DMODEL, DMODEL, false>
        <<<dim3(DMODEL / 128, BATCH * S_LEN / 128), 256, SMEM_GEMM>>>(
            attbuf, wbuf + 3 * DMODEL * DMODEL, out_b, out);
}

// round 14
// speedup vs baseline: 1.3766x; 1.1652x over previous
#include <cuda_runtime.h>
#include <cuda_fp16.h>
#include <cstdint>
#include <stdint.h>
#include <math.h>

#define S_LEN  2048
#define BATCH  2
#define DMODEL 1024
#define NH     16
#define HD     64

// Scratch (allocation-free requirement)
__device__ float  g_qkv[BATCH * S_LEN * 3 * DMODEL];       // [b, s, 3d] (tf32-rounded)
__device__ float  g_att[BATCH * S_LEN * DMODEL];           // features-rounded, then attn out
__device__ float  g_w[4 * DMODEL * DMODEL];                // rounded qkv_w | out_w
__device__ __half g_vh[BATCH * S_LEN * DMODEL];            // V in fp16, [token][d]

// ---------------------------------------------------------------------------
// helpers
// ---------------------------------------------------------------------------
__device__ __forceinline__ unsigned f2tf32(float f) {
    unsigned u;
    asm("cvt.rna.tf32.f32 %0, %1;" : "=r"(u) : "f"(f));
    return u;
}
__device__ __forceinline__ float tf32f(float f) {
    return __uint_as_float(f2tf32(f));
}
__device__ __forceinline__ unsigned packh2(float lo, float hi) {
    __half2 h = __floats2half2_rn(lo, hi);
    return *(unsigned*)&h;
}
__device__ __forceinline__ void mma_tf32(float c[4], unsigned a0, unsigned a1,
                                         unsigned a2, unsigned a3,
                                         unsigned b0, unsigned b1) {
    asm("mma.sync.aligned.m16n8k8.row.col.f32.tf32.tf32.f32 "
        "{%0,%1,%2,%3}, {%4,%5,%6,%7}, {%8,%9}, {%0,%1,%2,%3};"
        : "+f"(c[0]), "+f"(c[1]), "+f"(c[2]), "+f"(c[3])
        : "r"(a0), "r"(a1), "r"(a2), "r"(a3), "r"(b0), "r"(b1));
}
__device__ __forceinline__ void mma_f16(float c[4], unsigned a0, unsigned a1,
                                        unsigned a2, unsigned a3,
                                        unsigned b0, unsigned b1) {
    asm("mma.sync.aligned.m16n8k16.row.col.f32.f16.f16.f32 "
        "{%0,%1,%2,%3}, {%4,%5,%6,%7}, {%8,%9}, {%0,%1,%2,%3};"
        : "+f"(c[0]), "+f"(c[1]), "+f"(c[2]), "+f"(c[3])
        : "r"(a0), "r"(a1), "r"(a2), "r"(a3), "r"(b0), "r"(b1));
}
__device__ __forceinline__ void ldsm_x4(unsigned& r0, unsigned& r1,
                                        unsigned& r2, unsigned& r3, unsigned addr) {
    asm volatile("ldmatrix.sync.aligned.m8n8.x4.shared.b16 {%0,%1,%2,%3}, [%4];"
                 : "=r"(r0), "=r"(r1), "=r"(r2), "=r"(r3) : "r"(addr));
}
__device__ __forceinline__ void ldsm_x4t(unsigned& r0, unsigned& r1,
                                         unsigned& r2, unsigned& r3, unsigned addr) {
    asm volatile("ldmatrix.sync.aligned.m8n8.x4.trans.shared.b16 {%0,%1,%2,%3}, [%4];"
                 : "=r"(r0), "=r"(r1), "=r"(r2), "=r"(r3) : "r"(addr));
}
__device__ __forceinline__ void cp_async16(unsigned int dst, const void* src) {
    asm volatile("cp.async.cg.shared.global [%0], [%1], 16;" :: "r"(dst), "l"(src));
}
__device__ __forceinline__ void cp_commit() {
    asm volatile("cp.async.commit_group;");
}
template<int N>
__device__ __forceinline__ void cp_wait() {
    asm volatile("cp.async.wait_group %0;" :: "n"(N));
}

// ---------------------------------------------------------------------------
// Fused elementwise tf32 rounding for features | qkv_w | out_w (idempotent)
// ---------------------------------------------------------------------------
#define NF4  (BATCH * S_LEN * DMODEL / 4)
#define NW14 (3 * DMODEL * DMODEL / 4)
#define NW24 (DMODEL * DMODEL / 4)

__global__ void round_all_kernel(const float4* __restrict__ f,
                                 const float4* __restrict__ w1,
                                 const float4* __restrict__ w2,
                                 float4* __restrict__ of,
                                 float4* __restrict__ ow1,
                                 float4* __restrict__ ow2)
{
    int i = blockIdx.x * blockDim.x + threadIdx.x;
    const float4* src; float4* dst; int j;
    if (i < NF4)                { src = f;  dst = of;  j = i; }
    else if (i < NF4 + NW14)    { src = w1; dst = ow1; j = i - NF4; }
    else if (i < NF4 + NW14 + NW24) { src = w2; dst = ow2; j = i - NF4 - NW14; }
    else return;
    float4 v = src[j];
    v.x = tf32f(v.x); v.y = tf32f(v.y);
    v.z = tf32f(v.z); v.w = tf32f(v.w);
    dst[j] = v;
}

// ---------------------------------------------------------------------------
// TF32 tensor-core GEMM (R13): 256 thr, 8 warps (2M x 4N, 64x32 tile),
// 3-stage cp.async ring, packed-x4 ldmatrix for A and B-pairs.
// WRITE_VH: additionally emit fp16 copy of the V column range into vh.
// ---------------------------------------------------------------------------
#define GSTG (128 * 36)
#define GSTAGE (2 * GSTG)
#define GSTAGES 3

template<int N_, int K_, bool ROUND, bool WRITE_VH>
__global__ __launch_bounds__(256, 2)
void gemm_tc(const float* __restrict__ A, const float* __restrict__ B,
             const float* __restrict__ bias, float* __restrict__ C,
             __half* __restrict__ vh)
{
    extern __shared__ float sm[];
    const unsigned int smAddr = (unsigned int)__cvta_generic_to_shared(sm);

    const int tid  = threadIdx.x;
    const int warp = tid >> 5;
    const int lane = tid & 31;
    const int gid  = lane >> 2;
    const int tig  = lane & 3;
    const int warpM = (warp & 1) * 64;
    const int warpN = (warp >> 1) * 32;
    const int mBase = blockIdx.y * 128;
    const int nBase = blockIdx.x * 128;

    const int lg = lane >> 3;
    const int lr = lane & 7;
    const unsigned aLdsmBase =
        (unsigned)(((warpM + (lg & 1) * 8 + lr) * 36 + (lg >> 1) * 4) * 4);
    const unsigned bPairBase =
        (unsigned)(((warpN + (lg >> 1) * 8 + lr) * 36 + (lg & 1) * 4) * 4);

    int lrow[4], lcol[4];
    #pragma unroll
    for (int i = 0; i < 4; i++) {
        int s4 = tid + i * 256;
        lrow[i] = s4 >> 3;
        lcol[i] = (s4 & 7) * 4;
    }

    auto issue_stage = [&](int stage, int k0) {
        unsigned int aB = smAddr + stage * GSTAGE * 4;
        unsigned int bB = aB + GSTG * 4;
        #pragma unroll
        for (int i = 0; i < 4; i++) {
            unsigned int off = (lrow[i] * 36 + lcol[i]) * 4;
            cp_async16(aB + off, A + (size_t)(mBase + lrow[i]) * K_ + k0 + lcol[i]);
            cp_async16(bB + off, B + (size_t)(nBase + lrow[i]) * K_ + k0 + lcol[i]);
        }
    };

    float acc[16][4];
    #pragma unroll
    for (int i = 0; i < 16; i++)
        #pragma unroll
        for (int j = 0; j < 4; j++) acc[i][j] = 0.0f;

    const int kTiles = K_ / 32;
    #pragma unroll
    for (int s = 0; s < GSTAGES - 1; s++) {
        issue_stage(s, s * 32);
        cp_commit();
    }

    for (int kt = 0; kt < kTiles; kt++) {
        if (kt == kTiles - 1) cp_wait<0>();
        else                  cp_wait<GSTAGES - 2>();
        __syncthreads();
        if (kt + GSTAGES - 1 < kTiles) {
            issue_stage((kt + GSTAGES - 1) % GSTAGES, (kt + GSTAGES - 1) * 32);
            cp_commit();
        }

        const unsigned stA = smAddr + (kt % GSTAGES) * (GSTAGE * 4);
        const unsigned stB = stA + GSTG * 4;

        #pragma unroll
        for (int ks = 0; ks < 4; ks++) {
            unsigned afr[4][4];
            #pragma unroll
            for (int mt = 0; mt < 4; mt++)
                ldsm_x4(afr[mt][0], afr[mt][1], afr[mt][2], afr[mt][3],
                        stA + aLdsmBase + (unsigned)((mt * 16 * 36 + ks * 8) * 4));
            #pragma unroll
            for (int p = 0; p < 2; p++) {
                unsigned b00, b01, b10, b11;
                ldsm_x4(b00, b01, b10, b11,
                        stB + bPairBase + (unsigned)((p * 16 * 36 + ks * 8) * 4));
                #pragma unroll
                for (int mt = 0; mt < 4; mt++) {
                    mma_tf32(acc[mt * 4 + 2 * p], afr[mt][0], afr[mt][1],
                             afr[mt][2], afr[mt][3], b00, b01);
                    mma_tf32(acc[mt * 4 + 2 * p + 1], afr[mt][0], afr[mt][1],
                             afr[mt][2], afr[mt][3], b10, b11);
                }
            }
        }
    }

    #pragma unroll
    for (int mt = 0; mt < 4; mt++) {
        #pragma unroll
        for (int nt = 0; nt < 4; nt++) {
            int row  = mBase + warpM + mt * 16 + gid;
            int coln = nBase + warpN + nt * 8 + 2 * tig;
            float b0 = bias[coln], b1 = bias[coln + 1];
            float* acc4 = acc[mt * 4 + nt];
            float2 w0, w1;
            if (ROUND) {
                w0.x = tf32f(acc4[0] + b0); w0.y = tf32f(acc4[1] + b1);
                w1.x = tf32f(acc4[2] + b0); w1.y = tf32f(acc4[3] + b1);
            } else {
                w0.x = acc4[0] + b0; w0.y = acc4[1] + b1;
                w1.x = acc4[2] + b0; w1.y = acc4[3] + b1;
            }
            *(float2*)(C + (size_t)row * N_ + coln)       = w0;
            *(float2*)(C + (size_t)(row + 8) * N_ + coln) = w1;
            if (WRITE_VH && coln >= 2 * DMODEL) {
                int d = coln - 2 * DMODEL;
                __half2 h0 = __floats2half2_rn(w0.x, w0.y);
                __half2 h1 = __floats2half2_rn(w1.x, w1.y);
                *(__half2*)(vh + (size_t)row * DMODEL + d)       = h0;
                *(__half2*)(vh + (size_t)(row + 8) * DMODEL + d) = h1;
            }
        }
    }
}

// ---------------------------------------------------------------------------
// Flash attention: QK^T in tf32 (ldmatrix Q x4, K packed-pair x4),
// PV in fp16 (P = S C-frag repacked in registers, ZERO shuffles;
// V fp16 in smem, B-frags via ldmatrix.x4.trans). 2 CTAs/SM.
// ---------------------------------------------------------------------------
#define QLD 68
#define KLD 68
#define VLDH 72                       // halves per V row (64 + 8 pad)
#define Q_FLOATS (128 * QLD)
#define K_FLOATS (64 * KLD)
#define V_BYTES  (64 * VLDH * 2)      // 9216 bytes per V tile

__global__ __launch_bounds__(256, 2)
void flash_attn_tc(const float* __restrict__ qkv, const __half* __restrict__ vh,
                   float* __restrict__ out, const int* __restrict__ causal_flag)
{
    extern __shared__ float sm[];
    float* Qs = sm;
    const unsigned int smAddr = (unsigned int)__cvta_generic_to_shared(sm);
    const unsigned int kAddr0 = smAddr + Q_FLOATS * 4;
    const unsigned int vAddr0 = kAddr0 + 2 * K_FLOATS * 4;

    const int tid  = threadIdx.x;
    const int warp = tid >> 5;
    const int lane = tid & 31;
    const int gid  = lane >> 2;
    const int tig  = lane & 3;
    const int qBase = blockIdx.x * 128;
    const int h = blockIdx.y;
    const int b = blockIdx.z;
    const bool causal = (*causal_flag != 0);

    const int rowStride = 3 * DMODEL;
    const float* qp = qkv + (size_t)b * S_LEN * rowStride + h * HD;
    const float* kp = qp + DMODEL;
    const __half* vp = vh + (size_t)b * S_LEN * DMODEL + h * HD;

    const int lg = lane >> 3;
    const int lr = lane & 7;
    const unsigned qLdsmBase = smAddr +
        (unsigned)(((warp * 16 + (lg & 1) * 8 + lr) * QLD + (lg >> 1) * 4) * 4);
    const unsigned kPairBase =
        (unsigned)((((lg >> 1) * 8 + lr) * KLD + (lg & 1) * 4) * 4);
    // V trans x4: m0/m1 = k-low/high of d-block (dt2*2), m2/m3 = same for dt2*2+1
    const unsigned vLdsmBase =
        (unsigned)(((lg & 1) * 8 + lr) * (VLDH * 2) + (lg >> 1) * 16);

    // K tile: 1024 16B chunks -> 4/thread;  V tile: 512 chunks -> 2/thread
    int kn[4], kc[4];
    #pragma unroll
    for (int i = 0; i < 4; i++) {
        int s4 = tid + i * 256;
        kn[i] = s4 >> 4;
        kc[i] = (s4 & 15) * 4;
    }
    int vn[2], vc[2];
    #pragma unroll
    for (int i = 0; i < 2; i++) {
        int s4 = tid + i * 256;
        vn[i] = s4 >> 3;              // row 0..63
        vc[i] = (s4 & 7) * 8;         // half offset 0..56
    }
    auto issue_kv = [&](int buf, int kBase) {
        unsigned int kB = kAddr0 + buf * K_FLOATS * 4;
        unsigned int vB = vAddr0 + buf * V_BYTES;
        #pragma unroll
        for (int i = 0; i < 4; i++)
            cp_async16(kB + (kn[i] * KLD + kc[i]) * 4,
                       kp + (size_t)(kBase + kn[i]) * rowStride + kc[i]);
        #pragma unroll
        for (int i = 0; i < 2; i++)
            cp_async16(vB + (vn[i] * VLDH + vc[i]) * 2,
                       vp + (size_t)(kBase + vn[i]) * DMODEL + vc[i]);
    };

    int nTiles = S_LEN / 64;
    if (causal) nTiles = (qBase + 128) / 64;

    issue_kv(0, 0);
    cp_commit();

    // Q load with folded 1/8 scale (exact on tf32 values)
    #pragma unroll
    for (int i = 0; i < 8; i++) {
        int s4 = tid + i * 256;
        int m  = s4 >> 4;
        int c  = (s4 & 15) * 4;
        float4 v = *(const float4*)(qp + (size_t)(qBase + m) * rowStride + c);
        v.x *= 0.125f; v.y *= 0.125f; v.z *= 0.125f; v.w *= 0.125f;
        *(float4*)&Qs[m * QLD + c] = v;
    }

    float of[8][4];
    #pragma unroll
    for (int i = 0; i < 8; i++)
        #pragma unroll
        for (int j = 0; j < 4; j++) of[i][j] = 0.0f;
    float mrow0 = -1e30f, mrow1 = -1e30f, lrow0 = 0.0f, lrow1 = 0.0f;

    const int row0g = qBase + warp * 16 + gid;

    for (int t = 0; t < nTiles; t++) {
        const int kBase = t * 64;
        const int buf   = t & 1;

        cp_wait<0>();
        __syncthreads();
        if (t + 1 < nTiles) {
            issue_kv(1 - buf, kBase + 64);
            cp_commit();
        }

        const unsigned kStage = kAddr0 + buf * K_FLOATS * 4;
        const unsigned vStage = vAddr0 + buf * V_BYTES;

        // ---- Phase A: S = (Q/8) K^T (tf32, packed K pairs) ----
        float sc[8][4];
        #pragma unroll
        for (int i = 0; i < 8; i++)
            #pragma unroll
            for (int j = 0; j < 4; j++) sc[i][j] = 0.0f;

        #pragma unroll
        for (int ks = 0; ks < 8; ks++) {
            unsigned a0, a1, a2, a3;
            ldsm_x4(a0, a1, a2, a3, qLdsmBase + (unsigned)(ks * 32));
            #pragma unroll
            for (int p = 0; p < 4; p++) {
                unsigned b00, b01, b10, b11;
                ldsm_x4(b00, b01, b10, b11,
                        kStage + kPairBase + (unsigned)((p * 16 * KLD + ks * 8) * 4));
                mma_tf32(sc[2 * p],     a0, a1, a2, a3, b00, b01);
                mma_tf32(sc[2 * p + 1], a0, a1, a2, a3, b10, b11);
            }
        }

        // ---- online softmax ----
        float ml0 = -1e30f, ml1 = -1e30f;
        #pragma unroll
        for (int nt = 0; nt < 8; nt++) {
            int coln = kBase + nt * 8 + 2 * tig;
            #pragma unroll
            for (int cc = 0; cc < 4; cc++) {
                float v = sc[nt][cc];
                if (causal) {
                    int col = coln + (cc & 1);
                    int row = (cc < 2) ? row0g : (row0g + 8);
                    if (col > row) v = -1e30f;
                }
                sc[nt][cc] = v;
                if (cc < 2) ml0 = fmaxf(ml0, v);
                else        ml1 = fmaxf(ml1, v);
            }
        }
        #pragma unroll
        for (int off = 1; off < 4; off <<= 1) {
            ml0 = fmaxf(ml0, __shfl_xor_sync(0xffffffffu, ml0, off));
            ml1 = fmaxf(ml1, __shfl_xor_sync(0xffffffffu, ml1, off));
        }
        float mn0 = fmaxf(mrow0, ml0), mn1 = fmaxf(mrow1, ml1);
        float al0 = __expf(mrow0 - mn0), al1 = __expf(mrow1 - mn1);
        mrow0 = mn0; mrow1 = mn1;

        float rs0 = 0.0f, rs1 = 0.0f;
        #pragma unroll
        for (int nt = 0; nt < 8; nt++) {
            float p0 = __expf(sc[nt][0] - mn0);
            float p1 = __expf(sc[nt][1] - mn0);
            float p2 = __expf(sc[nt][2] - mn1);
            float p3 = __expf(sc[nt][3] - mn1);
            sc[nt][0] = p0; sc[nt][1] = p1; sc[nt][2] = p2; sc[nt][3] = p3;
            rs0 += p0 + p1; rs1 += p2 + p3;
        }
        #pragma unroll
        for (int off = 1; off < 4; off <<= 1) {
            rs0 += __shfl_xor_sync(0xffffffffu, rs0, off);
            rs1 += __shfl_xor_sync(0xffffffffu, rs1, off);
        }
        lrow0 = lrow0 * al0 + rs0;
        lrow1 = lrow1 * al1 + rs1;
        #pragma unroll
        for (int dt = 0; dt < 8; dt++) {
            of[dt][0] *= al0; of[dt][1] *= al0;
            of[dt][2] *= al1; of[dt][3] *= al1;
        }

        // ---- Phase B: O += P V (fp16 m16n8k16, zero-shuffle P) ----
        #pragma unroll
        for (int kt = 0; kt < 4; kt++) {             // 16 keys per step
            unsigned a0 = packh2(sc[2 * kt][0],     sc[2 * kt][1]);
            unsigned a1 = packh2(sc[2 * kt][2],     sc[2 * kt][3]);
            unsigned a2 = packh2(sc[2 * kt + 1][0], sc[2 * kt + 1][1]);
            unsigned a3 = packh2(sc[2 * kt + 1][2], sc[2 * kt + 1][3]);
            #pragma unroll
            for (int dp = 0; dp < 4; dp++) {         // d-block pairs
                unsigned b00, b01, b10, b11;
                ldsm_x4t(b00, b01, b10, b11,
                         vStage + vLdsmBase +
                         (unsigned)(kt * 16 * (VLDH * 2) + dp * 32));
                mma_f16(of[2 * dp],     a0, a1, a2, a3, b00, b01);
                mma_f16(of[2 * dp + 1], a0, a1, a2, a3, b10, b11);
            }
        }
    }

    // Epilogue: normalize, round to tf32 (gemm2 consumes without cvt)
    float inv0 = 1.0f / lrow0, inv1 = 1.0f / lrow1;
    float* op = out + (size_t)b * S_LEN * DMODEL + h * HD;
    #pragma unroll
    for (int dt = 0; dt < 8; dt++) {
        int col = dt * 8 + 2 * tig;
        float2 w0, w1;
        w0.x = tf32f(of[dt][0] * inv0); w0.y = tf32f(of[dt][1] * inv0);
        w1.x = tf32f(of[dt][2] * inv1); w1.y = tf32f(of[dt][3] * inv1);
        *(float2*)(op + (size_t)row0g * DMODEL + col)       = w0;
        *(float2*)(op + (size_t)(row0g + 8) * DMODEL + col) = w1;
    }
}

// ---------------------------------------------------------------------------
extern "C" void kernel_launch(void* const* d_in, const int* in_sizes, int n_in,
                              void* d_out, int out_size)
{
    (void)in_sizes; (void)n_in; (void)out_size;
    const float* features = (const float*)d_in[0];
    const float* qkv_w    = (const float*)d_in[1];
    const float* qkv_b    = (const float*)d_in[2];
    const float* out_w    = (const float*)d_in[3];
    const float* out_b    = (const float*)d_in[4];
    const int*   causal   = (const int*)d_in[5];
    float* out = (float*)d_out;

    float*  qkvbuf = nullptr;
    float*  attbuf = nullptr;
    float*  wbuf   = nullptr;
    __half* vhbuf  = nullptr;
    cudaGetSymbolAddress((void**)&qkvbuf, g_qkv);
    cudaGetSymbolAddress((void**)&attbuf, g_att);
    cudaGetSymbolAddress((void**)&wbuf,   g_w);
    cudaGetSymbolAddress((void**)&vhbuf,  g_vh);

    const int SMEM_GEMM  = GSTAGES * GSTAGE * (int)sizeof(float);   // 110592
    const int SMEM_FLASH = Q_FLOATS * 4 + 2 * K_FLOATS * 4 + 2 * V_BYTES; // 88064

    cudaFuncSetAttribute(gemm_tc<3 * DMODEL, DMODEL, true, true>,
                         cudaFuncAttributeMaxDynamicSharedMemorySize, SMEM_GEMM);
    cudaFuncSetAttribute(gemm_tc<DMODEL, DMODEL, false, false>,
                         cudaFuncAttributeMaxDynamicSharedMemorySize, SMEM_GEMM);
    cudaFuncSetAttribute(flash_attn_tc,
                         cudaFuncAttributeMaxDynamicSharedMemorySize, SMEM_FLASH);

    // 0) fused pre-rounding of all inputs to tf32 values
    {
        int total4 = NF4 + NW14 + NW24;
        round_all_kernel<<<(total4 + 255) / 256, 256>>>(
            (const float4*)features, (const float4*)qkv_w, (const float4*)out_w,
            (float4*)attbuf, (float4*)wbuf,
            (float4*)(wbuf + 3 * DMODEL * DMODEL));
    }

    // 1) QKV projection (rounded output; V also emitted as fp16)
    gemm_tc<3 * DMODEL, DMODEL, true, true>
        <<<dim3(3 * DMODEL / 128, BATCH * S_LEN / 128), 256, SMEM_GEMM>>>(
            attbuf, wbuf, qkv_b, qkvbuf, vhbuf);

    // 2) Attention (tf32 QK^T, fp16 PV)
    flash_attn_tc<<<dim3(S_LEN / 128, NH, BATCH), 256, SMEM_FLASH>>>(
        qkvbuf, vhbuf, attbuf, causal);

    // 3) Output projection (exact fp32 output)
    gemm_tc<DMODEL, DMODEL, false, false>
        <<<dim3(DMODEL / 128, BATCH * S_LEN / 128), 256, SMEM_GEMM>>>(
            attbuf, wbuf + 3 * DMODEL * DMODEL, out_b, out, nullptr);
}

// round 15
// speedup vs baseline: 1.5795x; 1.1474x over previous
#include <cuda_runtime.h>
#include <cuda_fp16.h>
#include <cstdint>
#include <stdint.h>
#include <math.h>

#define S_LEN  2048
#define BATCH  2
#define DMODEL 1024
#define NH     16
#define HD     64

// Scratch (allocation-free requirement)
__device__ float  g_att[BATCH * S_LEN * DMODEL];           // features-rounded, then attn out
__device__ float  g_w[4 * DMODEL * DMODEL];                // rounded qkv_w | out_w
__device__ __half g_qkvh[BATCH * S_LEN * 3 * DMODEL];      // fp16 QKV, Q pre-scaled by 1/8

// ---------------------------------------------------------------------------
// helpers
// ---------------------------------------------------------------------------
__device__ __forceinline__ unsigned f2tf32(float f) {
    unsigned u;
    asm("cvt.rna.tf32.f32 %0, %1;" : "=r"(u) : "f"(f));
    return u;
}
__device__ __forceinline__ float tf32f(float f) {
    return __uint_as_float(f2tf32(f));
}
__device__ __forceinline__ unsigned packh2(float lo, float hi) {
    __half2 h = __floats2half2_rn(lo, hi);
    return *(unsigned*)&h;
}
__device__ __forceinline__ void mma_tf32(float c[4], unsigned a0, unsigned a1,
                                         unsigned a2, unsigned a3,
                                         unsigned b0, unsigned b1) {
    asm("mma.sync.aligned.m16n8k8.row.col.f32.tf32.tf32.f32 "
        "{%0,%1,%2,%3}, {%4,%5,%6,%7}, {%8,%9}, {%0,%1,%2,%3};"
        : "+f"(c[0]), "+f"(c[1]), "+f"(c[2]), "+f"(c[3])
        : "r"(a0), "r"(a1), "r"(a2), "r"(a3), "r"(b0), "r"(b1));
}
__device__ __forceinline__ void mma_f16(float c[4], unsigned a0, unsigned a1,
                                        unsigned a2, unsigned a3,
                                        unsigned b0, unsigned b1) {
    asm("mma.sync.aligned.m16n8k16.row.col.f32.f16.f16.f32 "
        "{%0,%1,%2,%3}, {%4,%5,%6,%7}, {%8,%9}, {%0,%1,%2,%3};"
        : "+f"(c[0]), "+f"(c[1]), "+f"(c[2]), "+f"(c[3])
        : "r"(a0), "r"(a1), "r"(a2), "r"(a3), "r"(b0), "r"(b1));
}
__device__ __forceinline__ void ldsm_x4(unsigned& r0, unsigned& r1,
                                        unsigned& r2, unsigned& r3, unsigned addr) {
    asm volatile("ldmatrix.sync.aligned.m8n8.x4.shared.b16 {%0,%1,%2,%3}, [%4];"
                 : "=r"(r0), "=r"(r1), "=r"(r2), "=r"(r3) : "r"(addr));
}
__device__ __forceinline__ void ldsm_x4t(unsigned& r0, unsigned& r1,
                                         unsigned& r2, unsigned& r3, unsigned addr) {
    asm volatile("ldmatrix.sync.aligned.m8n8.x4.trans.shared.b16 {%0,%1,%2,%3}, [%4];"
                 : "=r"(r0), "=r"(r1), "=r"(r2), "=r"(r3) : "r"(addr));
}
__device__ __forceinline__ void cp_async16(unsigned int dst, const void* src) {
    asm volatile("cp.async.cg.shared.global [%0], [%1], 16;" :: "r"(dst), "l"(src));
}
__device__ __forceinline__ void cp_commit() {
    asm volatile("cp.async.commit_group;");
}
template<int N>
__device__ __forceinline__ void cp_wait() {
    asm volatile("cp.async.wait_group %0;" :: "n"(N));
}

// ---------------------------------------------------------------------------
// Fused elementwise tf32 rounding for features | qkv_w | out_w (idempotent)
// ---------------------------------------------------------------------------
#define NF4  (BATCH * S_LEN * DMODEL / 4)
#define NW14 (3 * DMODEL * DMODEL / 4)
#define NW24 (DMODEL * DMODEL / 4)

__global__ void round_all_kernel(const float4* __restrict__ f,
                                 const float4* __restrict__ w1,
                                 const float4* __restrict__ w2,
                                 float4* __restrict__ of,
                                 float4* __restrict__ ow1,
                                 float4* __restrict__ ow2)
{
    int i = blockIdx.x * blockDim.x + threadIdx.x;
    const float4* src; float4* dst; int j;
    if (i < NF4)                { src = f;  dst = of;  j = i; }
    else if (i < NF4 + NW14)    { src = w1; dst = ow1; j = i - NF4; }
    else if (i < NF4 + NW14 + NW24) { src = w2; dst = ow2; j = i - NF4 - NW14; }
    else return;
    float4 v = src[j];
    v.x = tf32f(v.x); v.y = tf32f(v.y);
    v.z = tf32f(v.z); v.w = tf32f(v.w);
    dst[j] = v;
}

// ---------------------------------------------------------------------------
// TF32 tensor-core GEMM (R13 shape): 256 thr, 8 warps (2M x 4N, 64x32 tile),
// 3-stage cp.async ring, packed-x4 ldmatrix for A and B-pairs.
// MODE 0: fp32 C output (out projection).
// MODE 1: fp16 QKV output (Q scaled by 1/8); no fp32 store.
// ---------------------------------------------------------------------------
#define GSTG (128 * 36)
#define GSTAGE (2 * GSTG)
#define GSTAGES 3

template<int N_, int K_, int MODE>
__global__ __launch_bounds__(256, 2)
void gemm_tc(const float* __restrict__ A, const float* __restrict__ B,
             const float* __restrict__ bias, float* __restrict__ C,
             __half* __restrict__ qkvh)
{
    extern __shared__ float sm[];
    const unsigned int smAddr = (unsigned int)__cvta_generic_to_shared(sm);

    const int tid  = threadIdx.x;
    const int warp = tid >> 5;
    const int lane = tid & 31;
    const int gid  = lane >> 2;
    const int tig  = lane & 3;
    const int warpM = (warp & 1) * 64;
    const int warpN = (warp >> 1) * 32;
    const int mBase = blockIdx.y * 128;
    const int nBase = blockIdx.x * 128;

    const int lg = lane >> 3;
    const int lr = lane & 7;
    const unsigned aLdsmBase =
        (unsigned)(((warpM + (lg & 1) * 8 + lr) * 36 + (lg >> 1) * 4) * 4);
    const unsigned bPairBase =
        (unsigned)(((warpN + (lg >> 1) * 8 + lr) * 36 + (lg & 1) * 4) * 4);

    int lrow[4], lcol[4];
    #pragma unroll
    for (int i = 0; i < 4; i++) {
        int s4 = tid + i * 256;
        lrow[i] = s4 >> 3;
        lcol[i] = (s4 & 7) * 4;
    }

    auto issue_stage = [&](int stage, int k0) {
        unsigned int aB = smAddr + stage * GSTAGE * 4;
        unsigned int bB = aB + GSTG * 4;
        #pragma unroll
        for (int i = 0; i < 4; i++) {
            unsigned int off = (lrow[i] * 36 + lcol[i]) * 4;
            cp_async16(aB + off, A + (size_t)(mBase + lrow[i]) * K_ + k0 + lcol[i]);
            cp_async16(bB + off, B + (size_t)(nBase + lrow[i]) * K_ + k0 + lcol[i]);
        }
    };

    float acc[16][4];
    #pragma unroll
    for (int i = 0; i < 16; i++)
        #pragma unroll
        for (int j = 0; j < 4; j++) acc[i][j] = 0.0f;

    const int kTiles = K_ / 32;
    #pragma unroll
    for (int s = 0; s < GSTAGES - 1; s++) {
        issue_stage(s, s * 32);
        cp_commit();
    }

    for (int kt = 0; kt < kTiles; kt++) {
        if (kt == kTiles - 1) cp_wait<0>();
        else                  cp_wait<GSTAGES - 2>();
        __syncthreads();
        if (kt + GSTAGES - 1 < kTiles) {
            issue_stage((kt + GSTAGES - 1) % GSTAGES, (kt + GSTAGES - 1) * 32);
            cp_commit();
        }

        const unsigned stA = smAddr + (kt % GSTAGES) * (GSTAGE * 4);
        const unsigned stB = stA + GSTG * 4;

        #pragma unroll
        for (int ks = 0; ks < 4; ks++) {
            unsigned afr[4][4];
            #pragma unroll
            for (int mt = 0; mt < 4; mt++)
                ldsm_x4(afr[mt][0], afr[mt][1], afr[mt][2], afr[mt][3],
                        stA + aLdsmBase + (unsigned)((mt * 16 * 36 + ks * 8) * 4));
            #pragma unroll
            for (int p = 0; p < 2; p++) {
                unsigned b00, b01, b10, b11;
                ldsm_x4(b00, b01, b10, b11,
                        stB + bPairBase + (unsigned)((p * 16 * 36 + ks * 8) * 4));
                #pragma unroll
                for (int mt = 0; mt < 4; mt++) {
                    mma_tf32(acc[mt * 4 + 2 * p], afr[mt][0], afr[mt][1],
                             afr[mt][2], afr[mt][3], b00, b01);
                    mma_tf32(acc[mt * 4 + 2 * p + 1], afr[mt][0], afr[mt][1],
                             afr[mt][2], afr[mt][3], b10, b11);
                }
            }
        }
    }

    #pragma unroll
    for (int mt = 0; mt < 4; mt++) {
        #pragma unroll
        for (int nt = 0; nt < 4; nt++) {
            int row  = mBase + warpM + mt * 16 + gid;
            int coln = nBase + warpN + nt * 8 + 2 * tig;
            float b0 = bias[coln], b1 = bias[coln + 1];
            float* acc4 = acc[mt * 4 + nt];
            float v00 = acc4[0] + b0, v01 = acc4[1] + b1;
            float v10 = acc4[2] + b0, v11 = acc4[3] + b1;
            if (MODE == 1) {
                float s = (coln < DMODEL) ? 0.125f : 1.0f;   // pre-scale Q
                __half2 h0 = __floats2half2_rn(v00 * s, v01 * s);
                __half2 h1 = __floats2half2_rn(v10 * s, v11 * s);
                *(__half2*)(qkvh + (size_t)row * N_ + coln)       = h0;
                *(__half2*)(qkvh + (size_t)(row + 8) * N_ + coln) = h1;
            } else {
                float2 w0 = {v00, v01}, w1 = {v10, v11};
                *(float2*)(C + (size_t)row * N_ + coln)       = w0;
                *(float2*)(C + (size_t)(row + 8) * N_ + coln) = w1;
            }
        }
    }
}

// ---------------------------------------------------------------------------
// Full fp16 flash attention (fp32 accumulate): QK^T and PV in m16n8k16.
// Q pre-scaled by 1/8 in gemm1 epilogue. Q/K/V fp16 smem, stride 72 halves
// (144B rows -> conflict-free ldmatrix). Zero-shuffle P repack. 2 CTAs/SM.
// ---------------------------------------------------------------------------
#define QLDH 72
#define KLDH 72
#define VLDH 72
#define Q_BYTES (128 * QLDH * 2)     // 18432
#define K_BYTES (64 * KLDH * 2)      // 9216
#define V_BYTES (64 * VLDH * 2)      // 9216

__global__ __launch_bounds__(256, 2)
void flash_attn_tc(const __half* __restrict__ qkvh, float* __restrict__ out,
                   const int* __restrict__ causal_flag)
{
    extern __shared__ float sm[];
    const unsigned int smAddr = (unsigned int)__cvta_generic_to_shared(sm);
    const unsigned int qAddr  = smAddr;
    const unsigned int kAddr0 = smAddr + Q_BYTES;
    const unsigned int vAddr0 = kAddr0 + 2 * K_BYTES;
    __half* Qs = (__half*)sm;

    const int tid  = threadIdx.x;
    const int warp = tid >> 5;
    const int lane = tid & 31;
    const int gid  = lane >> 2;
    const int tig  = lane & 3;
    const int qBase = blockIdx.x * 128;
    const int h = blockIdx.y;
    const int b = blockIdx.z;
    const bool causal = (*causal_flag != 0);

    const int rowStride = 3 * DMODEL;                 // halves
    const __half* qp = qkvh + (size_t)b * S_LEN * rowStride + h * HD;
    const __half* kp = qp + DMODEL;
    const __half* vp = qp + 2 * DMODEL;

    const int lg = lane >> 3;
    const int lr = lane & 7;
    // Q A-frag: lg0=(m0-7,klo) lg1=(m8-15,klo) lg2=(m0-7,khi) lg3=(m8-15,khi)
    const unsigned qLdsmBase = qAddr +
        (unsigned)((warp * 16 + (lg & 1) * 8 + lr) * (QLDH * 2) + (lg >> 1) * 16);
    // K B-pair: lg0=(nt,klo) lg1=(nt,khi) lg2=(nt+1,klo) lg3=(nt+1,khi)
    const unsigned kPairBase =
        (unsigned)(((lg >> 1) * 8 + lr) * (KLDH * 2) + (lg & 1) * 16);
    // V trans x4 (as R14)
    const unsigned vLdsmBase =
        (unsigned)(((lg & 1) * 8 + lr) * (VLDH * 2) + (lg >> 1) * 16);

    // K/V tiles: 64 rows x 64 halves = 512 16B-chunks -> 2/thread each
    int kn[2], kc[2];
    #pragma unroll
    for (int i = 0; i < 2; i++) {
        int s4 = tid + i * 256;
        kn[i] = s4 >> 3;              // row 0..63
        kc[i] = (s4 & 7) * 8;         // half col 0..56
    }
    auto issue_kv = [&](int buf, int kBase) {
        unsigned int kB = kAddr0 + buf * K_BYTES;
        unsigned int vB = vAddr0 + buf * V_BYTES;
        #pragma unroll
        for (int i = 0; i < 2; i++) {
            size_t g = (size_t)(kBase + kn[i]) * rowStride + kc[i];
            cp_async16(kB + (kn[i] * KLDH + kc[i]) * 2, kp + g);
            cp_async16(vB + (kn[i] * VLDH + kc[i]) * 2, vp + g);
        }
    };

    int nTiles = S_LEN / 64;
    if (causal) nTiles = (qBase + 128) / 64;

    issue_kv(0, 0);
    cp_commit();

    // Q tile: 128 rows x 64 halves = 1024 chunks -> 4/thread (already scaled)
    #pragma unroll
    for (int i = 0; i < 4; i++) {
        int s4 = tid + i * 256;
        int m  = s4 >> 3;
        int c  = (s4 & 7) * 8;
        *(float4*)&Qs[m * QLDH + c] =
            *(const float4*)(qp + (size_t)(qBase + m) * rowStride + c);
    }

    float of[8][4];
    #pragma unroll
    for (int i = 0; i < 8; i++)
        #pragma unroll
        for (int j = 0; j < 4; j++) of[i][j] = 0.0f;
    float mrow0 = -1e30f, mrow1 = -1e30f, lrow0 = 0.0f, lrow1 = 0.0f;

    const int row0g = qBase + warp * 16 + gid;

    for (int t = 0; t < nTiles; t++) {
        const int kBase = t * 64;
        const int buf   = t & 1;

        cp_wait<0>();
        __syncthreads();
        if (t + 1 < nTiles) {
            issue_kv(1 - buf, kBase + 64);
            cp_commit();
        }

        const unsigned kStage = kAddr0 + buf * K_BYTES;
        const unsigned vStage = vAddr0 + buf * V_BYTES;

        // ---- Phase A: S = (Q/8) K^T  (fp16 m16n8k16, 4 k-steps) ----
        float sc[8][4];
        #pragma unroll
        for (int i = 0; i < 8; i++)
            #pragma unroll
            for (int j = 0; j < 4; j++) sc[i][j] = 0.0f;

        #pragma unroll
        for (int ks = 0; ks < 4; ks++) {
            unsigned a0, a1, a2, a3;
            ldsm_x4(a0, a1, a2, a3, qLdsmBase + (unsigned)(ks * 32));
            #pragma unroll
            for (int p = 0; p < 4; p++) {
                unsigned b00, b01, b10, b11;
                ldsm_x4(b00, b01, b10, b11,
                        kStage + kPairBase +
                        (unsigned)(p * 16 * (KLDH * 2) + ks * 32));
                mma_f16(sc[2 * p],     a0, a1, a2, a3, b00, b01);
                mma_f16(sc[2 * p + 1], a0, a1, a2, a3, b10, b11);
            }
        }

        // ---- online softmax ----
        float ml0 = -1e30f, ml1 = -1e30f;
        #pragma unroll
        for (int nt = 0; nt < 8; nt++) {
            int coln = kBase + nt * 8 + 2 * tig;
            #pragma unroll
            for (int cc = 0; cc < 4; cc++) {
                float v = sc[nt][cc];
                if (causal) {
                    int col = coln + (cc & 1);
                    int row = (cc < 2) ? row0g : (row0g + 8);
                    if (col > row) v = -1e30f;
                }
                sc[nt][cc] = v;
                if (cc < 2) ml0 = fmaxf(ml0, v);
                else        ml1 = fmaxf(ml1, v);
            }
        }
        #pragma unroll
        for (int off = 1; off < 4; off <<= 1) {
            ml0 = fmaxf(ml0, __shfl_xor_sync(0xffffffffu, ml0, off));
            ml1 = fmaxf(ml1, __shfl_xor_sync(0xffffffffu, ml1, off));
        }
        float mn0 = fmaxf(mrow0, ml0), mn1 = fmaxf(mrow1, ml1);
        float al0 = __expf(mrow0 - mn0), al1 = __expf(mrow1 - mn1);
        mrow0 = mn0; mrow1 = mn1;

        float rs0 = 0.0f, rs1 = 0.0f;
        #pragma unroll
        for (int nt = 0; nt < 8; nt++) {
            float p0 = __expf(sc[nt][0] - mn0);
            float p1 = __expf(sc[nt][1] - mn0);
            float p2 = __expf(sc[nt][2] - mn1);
            float p3 = __expf(sc[nt][3] - mn1);
            sc[nt][0] = p0; sc[nt][1] = p1; sc[nt][2] = p2; sc[nt][3] = p3;
            rs0 += p0 + p1; rs1 += p2 + p3;
        }
        #pragma unroll
        for (int off = 1; off < 4; off <<= 1) {
            rs0 += __shfl_xor_sync(0xffffffffu, rs0, off);
            rs1 += __shfl_xor_sync(0xffffffffu, rs1, off);
        }
        lrow0 = lrow0 * al0 + rs0;
        lrow1 = lrow1 * al1 + rs1;
        #pragma unroll
        for (int dt = 0; dt < 8; dt++) {
            of[dt][0] *= al0; of[dt][1] *= al0;
            of[dt][2] *= al1; of[dt][3] *= al1;
        }

        // ---- Phase B: O += P V (fp16 m16n8k16, zero-shuffle P) ----
        #pragma unroll
        for (int kt = 0; kt < 4; kt++) {
            unsigned a0 = packh2(sc[2 * kt][0],     sc[2 * kt][1]);
            unsigned a1 = packh2(sc[2 * kt][2],     sc[2 * kt][3]);
            unsigned a2 = packh2(sc[2 * kt + 1][0], sc[2 * kt + 1][1]);
            unsigned a3 = packh2(sc[2 * kt + 1][2], sc[2 * kt + 1][3]);
            #pragma unroll
            for (int dp = 0; dp < 4; dp++) {
                unsigned b00, b01, b10, b11;
                ldsm_x4t(b00, b01, b10, b11,
                         vStage + vLdsmBase +
                         (unsigned)(kt * 16 * (VLDH * 2) + dp * 32));
                mma_f16(of[2 * dp],     a0, a1, a2, a3, b00, b01);
                mma_f16(of[2 * dp + 1], a0, a1, a2, a3, b10, b11);
            }
        }
    }

    // Epilogue: normalize, round to tf32 (gemm2 consumes without cvt)
    float inv0 = 1.0f / lrow0, inv1 = 1.0f / lrow1;
    float* op = out + (size_t)b * S_LEN * DMODEL + h * HD;
    #pragma unroll
    for (int dt = 0; dt < 8; dt++) {
        int col = dt * 8 + 2 * tig;
        float2 w0, w1;
        w0.x = tf32f(of[dt][0] * inv0); w0.y = tf32f(of[dt][1] * inv0);
        w1.x = tf32f(of[dt][2] * inv1); w1.y = tf32f(of[dt][3] * inv1);
        *(float2*)(op + (size_t)row0g * DMODEL + col)       = w0;
        *(float2*)(op + (size_t)(row0g + 8) * DMODEL + col) = w1;
    }
}

// ---------------------------------------------------------------------------
extern "C" void kernel_launch(void* const* d_in, const int* in_sizes, int n_in,
                              void* d_out, int out_size)
{
    (void)in_sizes; (void)n_in; (void)out_size;
    const float* features = (const float*)d_in[0];
    const float* qkv_w    = (const float*)d_in[1];
    const float* qkv_b    = (const float*)d_in[2];
    const float* out_w    = (const float*)d_in[3];
    const float* out_b    = (const float*)d_in[4];
    const int*   causal   = (const int*)d_in[5];
    float* out = (float*)d_out;

    float*  attbuf = nullptr;
    float*  wbuf   = nullptr;
    __half* qkvh   = nullptr;
    cudaGetSymbolAddress((void**)&attbuf, g_att);
    cudaGetSymbolAddress((void**)&wbuf,   g_w);
    cudaGetSymbolAddress((void**)&qkvh,   g_qkvh);

    const int SMEM_GEMM  = GSTAGES * GSTAGE * (int)sizeof(float);       // 110592
    const int SMEM_FLASH = Q_BYTES + 2 * K_BYTES + 2 * V_BYTES;         // 55296

    cudaFuncSetAttribute(gemm_tc<3 * DMODEL, DMODEL, 1>,
                         cudaFuncAttributeMaxDynamicSharedMemorySize, SMEM_GEMM);
    cudaFuncSetAttribute(gemm_tc<DMODEL, DMODEL, 0>,
                         cudaFuncAttributeMaxDynamicSharedMemorySize, SMEM_GEMM);
    cudaFuncSetAttribute(flash_attn_tc,
                         cudaFuncAttributeMaxDynamicSharedMemorySize, SMEM_FLASH);

    // 0) fused pre-rounding of all inputs to tf32 values
    {
        int total4 = NF4 + NW14 + NW24;
        round_all_kernel<<<(total4 + 255) / 256, 256>>>(
            (const float4*)features, (const float4*)qkv_w, (const float4*)out_w,
            (float4*)attbuf, (float4*)wbuf,
            (float4*)(wbuf + 3 * DMODEL * DMODEL));
    }

    // 1) QKV projection -> fp16 QKV (Q pre-scaled by 1/8)
    gemm_tc<3 * DMODEL, DMODEL, 1>
        <<<dim3(3 * DMODEL / 128, BATCH * S_LEN / 128), 256, SMEM_GEMM>>>(
            attbuf, wbuf, qkv_b, nullptr, qkvh);

    // 2) Attention (full fp16 MMA, fp32 accumulate)
    flash_attn_tc<<<dim3(S_LEN / 128, NH, BATCH), 256, SMEM_FLASH>>>(
        qkvh, attbuf, causal);

    // 3) Output projection (tf32, exact fp32 output)
    gemm_tc<DMODEL, DMODEL, 0>
        <<<dim3(DMODEL / 128, BATCH * S_LEN / 128), 256, SMEM_GEMM>>>(
            attbuf, wbuf + 3 * DMODEL * DMODEL, out_b, out, nullptr);
}

// round 16
// speedup vs baseline: 2.1906x; 1.3869x over previous
#include <cuda_runtime.h>
#include <cuda_fp16.h>
#include <cstdint>
#include <stdint.h>
#include <math.h>

#define S_LEN  2048
#define BATCH  2
#define DMODEL 1024
#define NH     16
#define HD     64

// Scratch (allocation-free requirement) — all-fp16 dataflow
__device__ __half g_fh[BATCH * S_LEN * DMODEL];            // features fp16
__device__ __half g_wh[4 * DMODEL * DMODEL];               // qkv_w | out_w fp16
__device__ __half g_qkvh[BATCH * S_LEN * 3 * DMODEL];      // QKV fp16, Q pre-scaled 1/8
__device__ __half g_atth[BATCH * S_LEN * DMODEL];          // attention output fp16

// ---------------------------------------------------------------------------
// helpers
// ---------------------------------------------------------------------------
__device__ __forceinline__ unsigned packh2(float lo, float hi) {
    __half2 h = __floats2half2_rn(lo, hi);
    return *(unsigned*)&h;
}
__device__ __forceinline__ void mma_f16(float c[4], unsigned a0, unsigned a1,
                                        unsigned a2, unsigned a3,
                                        unsigned b0, unsigned b1) {
    asm("mma.sync.aligned.m16n8k16.row.col.f32.f16.f16.f32 "
        "{%0,%1,%2,%3}, {%4,%5,%6,%7}, {%8,%9}, {%0,%1,%2,%3};"
        : "+f"(c[0]), "+f"(c[1]), "+f"(c[2]), "+f"(c[3])
        : "r"(a0), "r"(a1), "r"(a2), "r"(a3), "r"(b0), "r"(b1));
}
__device__ __forceinline__ void ldsm_x4(unsigned& r0, unsigned& r1,
                                        unsigned& r2, unsigned& r3, unsigned addr) {
    asm volatile("ldmatrix.sync.aligned.m8n8.x4.shared.b16 {%0,%1,%2,%3}, [%4];"
                 : "=r"(r0), "=r"(r1), "=r"(r2), "=r"(r3) : "r"(addr));
}
__device__ __forceinline__ void ldsm_x4t(unsigned& r0, unsigned& r1,
                                         unsigned& r2, unsigned& r3, unsigned addr) {
    asm volatile("ldmatrix.sync.aligned.m8n8.x4.trans.shared.b16 {%0,%1,%2,%3}, [%4];"
                 : "=r"(r0), "=r"(r1), "=r"(r2), "=r"(r3) : "r"(addr));
}
__device__ __forceinline__ void cp_async16(unsigned int dst, const void* src) {
    asm volatile("cp.async.cg.shared.global [%0], [%1], 16;" :: "r"(dst), "l"(src));
}
__device__ __forceinline__ void cp_commit() {
    asm volatile("cp.async.commit_group;");
}
template<int N>
__device__ __forceinline__ void cp_wait() {
    asm volatile("cp.async.wait_group %0;" :: "n"(N));
}

// ---------------------------------------------------------------------------
// Fused fp32 -> fp16 conversion for features | qkv_w | out_w
// ---------------------------------------------------------------------------
#define NF4  (BATCH * S_LEN * DMODEL / 4)
#define NW14 (3 * DMODEL * DMODEL / 4)
#define NW24 (DMODEL * DMODEL / 4)

__global__ void to_half_kernel(const float4* __restrict__ f,
                               const float4* __restrict__ w1,
                               const float4* __restrict__ w2,
                               __half* __restrict__ of,
                               __half* __restrict__ ow1,
                               __half* __restrict__ ow2)
{
    int i = blockIdx.x * blockDim.x + threadIdx.x;
    const float4* src; __half* dst; int j;
    if (i < NF4)                    { src = f;  dst = of;  j = i; }
    else if (i < NF4 + NW14)        { src = w1; dst = ow1; j = i - NF4; }
    else if (i < NF4 + NW14 + NW24) { src = w2; dst = ow2; j = i - NF4 - NW14; }
    else return;
    float4 v = src[j];
    __half2 h0 = __floats2half2_rn(v.x, v.y);
    __half2 h1 = __floats2half2_rn(v.z, v.w);
    ((__half2*)dst)[j * 2]     = h0;
    ((__half2*)dst)[j * 2 + 1] = h1;
}

// ---------------------------------------------------------------------------
// FP16 tensor-core GEMM (fp32 accumulate): 256 thr, 8 warps (2M x 4N,
// 64x32 warp tile), BK=64, 3-stage cp.async ring, b16 ldmatrix.
// C[M,N] = A[M,K]*B[N,K]^T + bias[N].
// MODE 1: fp16 QKV output (Q columns scaled by 1/8).
// MODE 0: exact fp32 output.
// ---------------------------------------------------------------------------
#define HSTRIDE 72                        // halves per smem row (64 + 8 pad)
#define HTILE (128 * HSTRIDE)             // halves per (A or B) tile
#define HSTG_BYTES (2 * HTILE * 2)        // 36864 bytes per stage
#define GSTAGES 3

template<int N_, int K_, int MODE>
__global__ __launch_bounds__(256, 2)
void gemm_f16(const __half* __restrict__ A, const __half* __restrict__ B,
              const float* __restrict__ bias, float* __restrict__ C,
              __half* __restrict__ Ch)
{
    extern __shared__ float sm[];
    const unsigned int smAddr = (unsigned int)__cvta_generic_to_shared(sm);

    const int tid  = threadIdx.x;
    const int warp = tid >> 5;
    const int lane = tid & 31;
    const int gid  = lane >> 2;
    const int tig  = lane & 3;
    const int warpM = (warp & 1) * 64;
    const int warpN = (warp >> 1) * 32;
    const int mBase = blockIdx.y * 128;
    const int nBase = blockIdx.x * 128;

    const int lg = lane >> 3;
    const int lr = lane & 7;
    // A x4: (m0-7,klo)(m8-15,klo)(m0-7,khi)(m8-15,khi)
    const unsigned aLdsmBase =
        (unsigned)(((warpM + (lg & 1) * 8 + lr) * HSTRIDE + (lg >> 1) * 8) * 2);
    // B pair x4: (nt,klo)(nt,khi)(nt+1,klo)(nt+1,khi)
    const unsigned bPairBase =
        (unsigned)(((warpN + (lg >> 1) * 8 + lr) * HSTRIDE + (lg & 1) * 8) * 2);

    // 128 rows x 64 halves = 1024 16B chunks per tile -> 4/thread
    int lrow[4], lcol[4];
    #pragma unroll
    for (int i = 0; i < 4; i++) {
        int s4 = tid + i * 256;
        lrow[i] = s4 >> 3;
        lcol[i] = (s4 & 7) * 8;           // half offset
    }

    auto issue_stage = [&](int stage, int k0) {
        unsigned int aB = smAddr + stage * HSTG_BYTES;
        unsigned int bB = aB + HTILE * 2;
        #pragma unroll
        for (int i = 0; i < 4; i++) {
            unsigned int off = (lrow[i] * HSTRIDE + lcol[i]) * 2;
            cp_async16(aB + off, A + (size_t)(mBase + lrow[i]) * K_ + k0 + lcol[i]);
            cp_async16(bB + off, B + (size_t)(nBase + lrow[i]) * K_ + k0 + lcol[i]);
        }
    };

    float acc[16][4];
    #pragma unroll
    for (int i = 0; i < 16; i++)
        #pragma unroll
        for (int j = 0; j < 4; j++) acc[i][j] = 0.0f;

    const int kTiles = K_ / 64;
    #pragma unroll
    for (int s = 0; s < GSTAGES - 1; s++) {
        issue_stage(s, s * 64);
        cp_commit();
    }

    for (int kt = 0; kt < kTiles; kt++) {
        if (kt == kTiles - 1) cp_wait<0>();
        else                  cp_wait<GSTAGES - 2>();
        __syncthreads();
        if (kt + GSTAGES - 1 < kTiles) {
            issue_stage((kt + GSTAGES - 1) % GSTAGES, (kt + GSTAGES - 1) * 64);
            cp_commit();
        }

        const unsigned stA = smAddr + (kt % GSTAGES) * HSTG_BYTES;
        const unsigned stB = stA + HTILE * 2;

        #pragma unroll
        for (int ks = 0; ks < 4; ks++) {          // 4 x k16 per BK=64
            unsigned afr[4][4];
            #pragma unroll
            for (int mt = 0; mt < 4; mt++)
                ldsm_x4(afr[mt][0], afr[mt][1], afr[mt][2], afr[mt][3],
                        stA + aLdsmBase +
                        (unsigned)(mt * 16 * HSTRIDE * 2 + ks * 32));
            #pragma unroll
            for (int p = 0; p < 2; p++) {
                unsigned b00, b01, b10, b11;
                ldsm_x4(b00, b01, b10, b11,
                        stB + bPairBase +
                        (unsigned)(p * 16 * HSTRIDE * 2 + ks * 32));
                #pragma unroll
                for (int mt = 0; mt < 4; mt++) {
                    mma_f16(acc[mt * 4 + 2 * p], afr[mt][0], afr[mt][1],
                            afr[mt][2], afr[mt][3], b00, b01);
                    mma_f16(acc[mt * 4 + 2 * p + 1], afr[mt][0], afr[mt][1],
                            afr[mt][2], afr[mt][3], b10, b11);
                }
            }
        }
    }

    #pragma unroll
    for (int mt = 0; mt < 4; mt++) {
        #pragma unroll
        for (int nt = 0; nt < 4; nt++) {
            int row  = mBase + warpM + mt * 16 + gid;
            int coln = nBase + warpN + nt * 8 + 2 * tig;
            float b0 = bias[coln], b1 = bias[coln + 1];
            float* acc4 = acc[mt * 4 + nt];
            float v00 = acc4[0] + b0, v01 = acc4[1] + b1;
            float v10 = acc4[2] + b0, v11 = acc4[3] + b1;
            if (MODE == 1) {
                float s = (coln < DMODEL) ? 0.125f : 1.0f;   // pre-scale Q
                __half2 h0 = __floats2half2_rn(v00 * s, v01 * s);
                __half2 h1 = __floats2half2_rn(v10 * s, v11 * s);
                *(__half2*)(Ch + (size_t)row * N_ + coln)       = h0;
                *(__half2*)(Ch + (size_t)(row + 8) * N_ + coln) = h1;
            } else {
                float2 w0 = {v00, v01}, w1 = {v10, v11};
                *(float2*)(C + (size_t)row * N_ + coln)       = w0;
                *(float2*)(C + (size_t)(row + 8) * N_ + coln) = w1;
            }
        }
    }
}

// ---------------------------------------------------------------------------
// Full fp16 flash attention (fp32 accumulate), as R15; epilogue emits fp16.
// ---------------------------------------------------------------------------
#define QLDH 72
#define KLDH 72
#define VLDH 72
#define Q_BYTES (128 * QLDH * 2)
#define K_BYTES (64 * KLDH * 2)
#define V_BYTES (64 * VLDH * 2)

__global__ __launch_bounds__(256, 2)
void flash_attn_tc(const __half* __restrict__ qkvh, __half* __restrict__ outh,
                   const int* __restrict__ causal_flag)
{
    extern __shared__ float sm[];
    const unsigned int smAddr = (unsigned int)__cvta_generic_to_shared(sm);
    const unsigned int kAddr0 = smAddr + Q_BYTES;
    const unsigned int vAddr0 = kAddr0 + 2 * K_BYTES;
    __half* Qs = (__half*)sm;

    const int tid  = threadIdx.x;
    const int warp = tid >> 5;
    const int lane = tid & 31;
    const int gid  = lane >> 2;
    const int tig  = lane & 3;
    const int qBase = blockIdx.x * 128;
    const int h = blockIdx.y;
    const int b = blockIdx.z;
    const bool causal = (*causal_flag != 0);

    const int rowStride = 3 * DMODEL;
    const __half* qp = qkvh + (size_t)b * S_LEN * rowStride + h * HD;
    const __half* kp = qp + DMODEL;
    const __half* vp = qp + 2 * DMODEL;

    const int lg = lane >> 3;
    const int lr = lane & 7;
    const unsigned qLdsmBase = smAddr +
        (unsigned)((warp * 16 + (lg & 1) * 8 + lr) * (QLDH * 2) + (lg >> 1) * 16);
    const unsigned kPairBase =
        (unsigned)(((lg >> 1) * 8 + lr) * (KLDH * 2) + (lg & 1) * 16);
    const unsigned vLdsmBase =
        (unsigned)(((lg & 1) * 8 + lr) * (VLDH * 2) + (lg >> 1) * 16);

    int kn[2], kc[2];
    #pragma unroll
    for (int i = 0; i < 2; i++) {
        int s4 = tid + i * 256;
        kn[i] = s4 >> 3;
        kc[i] = (s4 & 7) * 8;
    }
    auto issue_kv = [&](int buf, int kBase) {
        unsigned int kB = kAddr0 + buf * K_BYTES;
        unsigned int vB = vAddr0 + buf * V_BYTES;
        #pragma unroll
        for (int i = 0; i < 2; i++) {
            size_t g = (size_t)(kBase + kn[i]) * rowStride + kc[i];
            cp_async16(kB + (kn[i] * KLDH + kc[i]) * 2, kp + g);
            cp_async16(vB + (kn[i] * VLDH + kc[i]) * 2, vp + g);
        }
    };

    int nTiles = S_LEN / 64;
    if (causal) nTiles = (qBase + 128) / 64;

    issue_kv(0, 0);
    cp_commit();

    #pragma unroll
    for (int i = 0; i < 4; i++) {
        int s4 = tid + i * 256;
        int m  = s4 >> 3;
        int c  = (s4 & 7) * 8;
        *(float4*)&Qs[m * QLDH + c] =
            *(const float4*)(qp + (size_t)(qBase + m) * rowStride + c);
    }

    float of[8][4];
    #pragma unroll
    for (int i = 0; i < 8; i++)
        #pragma unroll
        for (int j = 0; j < 4; j++) of[i][j] = 0.0f;
    float mrow0 = -1e30f, mrow1 = -1e30f, lrow0 = 0.0f, lrow1 = 0.0f;

    const int row0g = qBase + warp * 16 + gid;

    for (int t = 0; t < nTiles; t++) {
        const int kBase = t * 64;
        const int buf   = t & 1;

        cp_wait<0>();
        __syncthreads();
        if (t + 1 < nTiles) {
            issue_kv(1 - buf, kBase + 64);
            cp_commit();
        }

        const unsigned kStage = kAddr0 + buf * K_BYTES;
        const unsigned vStage = vAddr0 + buf * V_BYTES;

        float sc[8][4];
        #pragma unroll
        for (int i = 0; i < 8; i++)
            #pragma unroll
            for (int j = 0; j < 4; j++) sc[i][j] = 0.0f;

        #pragma unroll
        for (int ks = 0; ks < 4; ks++) {
            unsigned a0, a1, a2, a3;
            ldsm_x4(a0, a1, a2, a3, qLdsmBase + (unsigned)(ks * 32));
            #pragma unroll
            for (int p = 0; p < 4; p++) {
                unsigned b00, b01, b10, b11;
                ldsm_x4(b00, b01, b10, b11,
                        kStage + kPairBase +
                        (unsigned)(p * 16 * (KLDH * 2) + ks * 32));
                mma_f16(sc[2 * p],     a0, a1, a2, a3, b00, b01);
                mma_f16(sc[2 * p + 1], a0, a1, a2, a3, b10, b11);
            }
        }

        float ml0 = -1e30f, ml1 = -1e30f;
        #pragma unroll
        for (int nt = 0; nt < 8; nt++) {
            int coln = kBase + nt * 8 + 2 * tig;
            #pragma unroll
            for (int cc = 0; cc < 4; cc++) {
                float v = sc[nt][cc];
                if (causal) {
                    int col = coln + (cc & 1);
                    int row = (cc < 2) ? row0g : (row0g + 8);
                    if (col > row) v = -1e30f;
                }
                sc[nt][cc] = v;
                if (cc < 2) ml0 = fmaxf(ml0, v);
                else        ml1 = fmaxf(ml1, v);
            }
        }
        #pragma unroll
        for (int off = 1; off < 4; off <<= 1) {
            ml0 = fmaxf(ml0, __shfl_xor_sync(0xffffffffu, ml0, off));
            ml1 = fmaxf(ml1, __shfl_xor_sync(0xffffffffu, ml1, off));
        }
        float mn0 = fmaxf(mrow0, ml0), mn1 = fmaxf(mrow1, ml1);
        float al0 = __expf(mrow0 - mn0), al1 = __expf(mrow1 - mn1);
        mrow0 = mn0; mrow1 = mn1;

        float rs0 = 0.0f, rs1 = 0.0f;
        #pragma unroll
        for (int nt = 0; nt < 8; nt++) {
            float p0 = __expf(sc[nt][0] - mn0);
            float p1 = __expf(sc[nt][1] - mn0);
            float p2 = __expf(sc[nt][2] - mn1);
            float p3 = __expf(sc[nt][3] - mn1);
            sc[nt][0] = p0; sc[nt][1] = p1; sc[nt][2] = p2; sc[nt][3] = p3;
            rs0 += p0 + p1; rs1 += p2 + p3;
        }
        #pragma unroll
        for (int off = 1; off < 4; off <<= 1) {
            rs0 += __shfl_xor_sync(0xffffffffu, rs0, off);
            rs1 += __shfl_xor_sync(0xffffffffu, rs1, off);
        }
        lrow0 = lrow0 * al0 + rs0;
        lrow1 = lrow1 * al1 + rs1;
        #pragma unroll
        for (int dt = 0; dt < 8; dt++) {
            of[dt][0] *= al0; of[dt][1] *= al0;
            of[dt][2] *= al1; of[dt][3] *= al1;
        }

        #pragma unroll
        for (int kt = 0; kt < 4; kt++) {
            unsigned a0 = packh2(sc[2 * kt][0],     sc[2 * kt][1]);
            unsigned a1 = packh2(sc[2 * kt][2],     sc[2 * kt][3]);
            unsigned a2 = packh2(sc[2 * kt + 1][0], sc[2 * kt + 1][1]);
            unsigned a3 = packh2(sc[2 * kt + 1][2], sc[2 * kt + 1][3]);
            #pragma unroll
            for (int dp = 0; dp < 4; dp++) {
                unsigned b00, b01, b10, b11;
                ldsm_x4t(b00, b01, b10, b11,
                         vStage + vLdsmBase +
                         (unsigned)(kt * 16 * (VLDH * 2) + dp * 32));
                mma_f16(of[2 * dp],     a0, a1, a2, a3, b00, b01);
                mma_f16(of[2 * dp + 1], a0, a1, a2, a3, b10, b11);
            }
        }
    }

    // Epilogue: normalize, emit fp16 for gemm2
    float inv0 = 1.0f / lrow0, inv1 = 1.0f / lrow1;
    __half* op = outh + (size_t)b * S_LEN * DMODEL + h * HD;
    #pragma unroll
    for (int dt = 0; dt < 8; dt++) {
        int col = dt * 8 + 2 * tig;
        __half2 h0 = __floats2half2_rn(of[dt][0] * inv0, of[dt][1] * inv0);
        __half2 h1 = __floats2half2_rn(of[dt][2] * inv1, of[dt][3] * inv1);
        *(__half2*)(op + (size_t)row0g * DMODEL + col)       = h0;
        *(__half2*)(op + (size_t)(row0g + 8) * DMODEL + col) = h1;
    }
}

// ---------------------------------------------------------------------------
extern "C" void kernel_launch(void* const* d_in, const int* in_sizes, int n_in,
                              void* d_out, int out_size)
{
    (void)in_sizes; (void)n_in; (void)out_size;
    const float* features = (const float*)d_in[0];
    const float* qkv_w    = (const float*)d_in[1];
    const float* qkv_b    = (const float*)d_in[2];
    const float* out_w    = (const float*)d_in[3];
    const float* out_b    = (const float*)d_in[4];
    const int*   causal   = (const int*)d_in[5];
    float* out = (float*)d_out;

    __half* fh    = nullptr;
    __half* wh    = nullptr;
    __half* qkvh  = nullptr;
    __half* atth  = nullptr;
    cudaGetSymbolAddress((void**)&fh,   g_fh);
    cudaGetSymbolAddress((void**)&wh,   g_wh);
    cudaGetSymbolAddress((void**)&qkvh, g_qkvh);
    cudaGetSymbolAddress((void**)&atth, g_atth);

    const int SMEM_GEMM  = GSTAGES * HSTG_BYTES;                    // 110592
    const int SMEM_FLASH = Q_BYTES + 2 * K_BYTES + 2 * V_BYTES;     // 55296

    cudaFuncSetAttribute(gemm_f16<3 * DMODEL, DMODEL, 1>,
                         cudaFuncAttributeMaxDynamicSharedMemorySize, SMEM_GEMM);
    cudaFuncSetAttribute(gemm_f16<DMODEL, DMODEL, 0>,
                         cudaFuncAttributeMaxDynamicSharedMemorySize, SMEM_GEMM);
    cudaFuncSetAttribute(flash_attn_tc,
                         cudaFuncAttributeMaxDynamicSharedMemorySize, SMEM_FLASH);

    // 0) fp32 -> fp16 conversion of all inputs
    {
        int total4 = NF4 + NW14 + NW24;
        to_half_kernel<<<(total4 + 255) / 256, 256>>>(
            (const float4*)features, (const float4*)qkv_w, (const float4*)out_w,
            fh, wh, wh + 3 * DMODEL * DMODEL);
    }

    // 1) QKV projection (fp16 MMA) -> fp16 QKV, Q pre-scaled by 1/8
    gemm_f16<3 * DMODEL, DMODEL, 1>
        <<<dim3(3 * DMODEL / 128, BATCH * S_LEN / 128), 256, SMEM_GEMM>>>(
            fh, wh, qkv_b, nullptr, qkvh);

    // 2) Attention (fp16 MMA, fp32 accumulate) -> fp16 output
    flash_attn_tc<<<dim3(S_LEN / 128, NH, BATCH), 256, SMEM_FLASH>>>(
        qkvh, atth, causal);

    // 3) Output projection (fp16 MMA, exact fp32 output)
    gemm_f16<DMODEL, DMODEL, 0>
        <<<dim3(DMODEL / 128, BATCH * S_LEN / 128), 256, SMEM_GEMM>>>(
            atth, wh + 3 * DMODEL * DMODEL, out_b, out, nullptr);
}

// round 17
// speedup vs baseline: 2.2192x; 1.0131x over previous
#include <cuda_runtime.h>
#include <cuda_fp16.h>
#include <cstdint>
#include <stdint.h>
#include <math.h>

#define S_LEN  2048
#define BATCH  2
#define DMODEL 1024
#define NH     16
#define HD     64

// Scratch (allocation-free requirement) — all-fp16 dataflow
__device__ __half g_fh[BATCH * S_LEN * DMODEL];            // features fp16
__device__ __half g_wh[4 * DMODEL * DMODEL];               // qkv_w | out_w fp16
__device__ __half g_qkvh[BATCH * S_LEN * 3 * DMODEL];      // QKV fp16, Q pre-scaled 1/8
__device__ __half g_atth[BATCH * S_LEN * DMODEL];          // attention output fp16

// ---------------------------------------------------------------------------
// helpers
// ---------------------------------------------------------------------------
__device__ __forceinline__ unsigned packh2(float lo, float hi) {
    __half2 h = __floats2half2_rn(lo, hi);
    return *(unsigned*)&h;
}
__device__ __forceinline__ void mma_f16(float c[4], unsigned a0, unsigned a1,
                                        unsigned a2, unsigned a3,
                                        unsigned b0, unsigned b1) {
    asm("mma.sync.aligned.m16n8k16.row.col.f32.f16.f16.f32 "
        "{%0,%1,%2,%3}, {%4,%5,%6,%7}, {%8,%9}, {%0,%1,%2,%3};"
        : "+f"(c[0]), "+f"(c[1]), "+f"(c[2]), "+f"(c[3])
        : "r"(a0), "r"(a1), "r"(a2), "r"(a3), "r"(b0), "r"(b1));
}
__device__ __forceinline__ void ldsm_x4(unsigned& r0, unsigned& r1,
                                        unsigned& r2, unsigned& r3, unsigned addr) {
    asm volatile("ldmatrix.sync.aligned.m8n8.x4.shared.b16 {%0,%1,%2,%3}, [%4];"
                 : "=r"(r0), "=r"(r1), "=r"(r2), "=r"(r3) : "r"(addr));
}
__device__ __forceinline__ void ldsm_x4t(unsigned& r0, unsigned& r1,
                                         unsigned& r2, unsigned& r3, unsigned addr) {
    asm volatile("ldmatrix.sync.aligned.m8n8.x4.trans.shared.b16 {%0,%1,%2,%3}, [%4];"
                 : "=r"(r0), "=r"(r1), "=r"(r2), "=r"(r3) : "r"(addr));
}
__device__ __forceinline__ void cp_async16(unsigned int dst, const void* src) {
    asm volatile("cp.async.cg.shared.global [%0], [%1], 16;" :: "r"(dst), "l"(src));
}
__device__ __forceinline__ void cp_commit() {
    asm volatile("cp.async.commit_group;");
}
template<int N>
__device__ __forceinline__ void cp_wait() {
    asm volatile("cp.async.wait_group %0;" :: "n"(N));
}

// ---------------------------------------------------------------------------
// Fused fp32 -> fp16 conversion for features | qkv_w | out_w
// ---------------------------------------------------------------------------
#define NF4  (BATCH * S_LEN * DMODEL / 4)
#define NW14 (3 * DMODEL * DMODEL / 4)
#define NW24 (DMODEL * DMODEL / 4)

__global__ void to_half_kernel(const float4* __restrict__ f,
                               const float4* __restrict__ w1,
                               const float4* __restrict__ w2,
                               __half* __restrict__ of,
                               __half* __restrict__ ow1,
                               __half* __restrict__ ow2)
{
    int i = blockIdx.x * blockDim.x + threadIdx.x;
    const float4* src; __half* dst; int j;
    if (i < NF4)                    { src = f;  dst = of;  j = i; }
    else if (i < NF4 + NW14)        { src = w1; dst = ow1; j = i - NF4; }
    else if (i < NF4 + NW14 + NW24) { src = w2; dst = ow2; j = i - NF4 - NW14; }
    else return;
    float4 v = src[j];
    __half2 h0 = __floats2half2_rn(v.x, v.y);
    __half2 h1 = __floats2half2_rn(v.z, v.w);
    ((__half2*)dst)[j * 2]     = h0;
    ((__half2*)dst)[j * 2 + 1] = h1;
}

// ---------------------------------------------------------------------------
// FP16 tensor-core GEMM (fp32 accumulate): 256 thr, 8 warps (2M x 4N,
// 64x32 warp tile), BK=64, 3-stage cp.async ring, b16 ldmatrix.
// MODE 1: fp16 QKV output (Q columns scaled by 1/8).  MODE 0: fp32 output.
// ---------------------------------------------------------------------------
#define HSTRIDE 72
#define HTILE (128 * HSTRIDE)
#define HSTG_BYTES (2 * HTILE * 2)
#define GSTAGES 3

template<int N_, int K_, int MODE>
__global__ __launch_bounds__(256, 2)
void gemm_f16(const __half* __restrict__ A, const __half* __restrict__ B,
              const float* __restrict__ bias, float* __restrict__ C,
              __half* __restrict__ Ch)
{
    extern __shared__ float sm[];
    const unsigned int smAddr = (unsigned int)__cvta_generic_to_shared(sm);

    const int tid  = threadIdx.x;
    const int warp = tid >> 5;
    const int lane = tid & 31;
    const int gid  = lane >> 2;
    const int tig  = lane & 3;
    const int warpM = (warp & 1) * 64;
    const int warpN = (warp >> 1) * 32;
    const int mBase = blockIdx.y * 128;
    const int nBase = blockIdx.x * 128;

    const int lg = lane >> 3;
    const int lr = lane & 7;
    const unsigned aLdsmBase =
        (unsigned)(((warpM + (lg & 1) * 8 + lr) * HSTRIDE + (lg >> 1) * 8) * 2);
    const unsigned bPairBase =
        (unsigned)(((warpN + (lg >> 1) * 8 + lr) * HSTRIDE + (lg & 1) * 8) * 2);

    int lrow[4], lcol[4];
    #pragma unroll
    for (int i = 0; i < 4; i++) {
        int s4 = tid + i * 256;
        lrow[i] = s4 >> 3;
        lcol[i] = (s4 & 7) * 8;
    }

    auto issue_stage = [&](int stage, int k0) {
        unsigned int aB = smAddr + stage * HSTG_BYTES;
        unsigned int bB = aB + HTILE * 2;
        #pragma unroll
        for (int i = 0; i < 4; i++) {
            unsigned int off = (lrow[i] * HSTRIDE + lcol[i]) * 2;
            cp_async16(aB + off, A + (size_t)(mBase + lrow[i]) * K_ + k0 + lcol[i]);
            cp_async16(bB + off, B + (size_t)(nBase + lrow[i]) * K_ + k0 + lcol[i]);
        }
    };

    float acc[16][4];
    #pragma unroll
    for (int i = 0; i < 16; i++)
        #pragma unroll
        for (int j = 0; j < 4; j++) acc[i][j] = 0.0f;

    const int kTiles = K_ / 64;
    #pragma unroll
    for (int s = 0; s < GSTAGES - 1; s++) {
        issue_stage(s, s * 64);
        cp_commit();
    }

    for (int kt = 0; kt < kTiles; kt++) {
        if (kt == kTiles - 1) cp_wait<0>();
        else                  cp_wait<GSTAGES - 2>();
        __syncthreads();
        if (kt + GSTAGES - 1 < kTiles) {
            issue_stage((kt + GSTAGES - 1) % GSTAGES, (kt + GSTAGES - 1) * 64);
            cp_commit();
        }

        const unsigned stA = smAddr + (kt % GSTAGES) * HSTG_BYTES;
        const unsigned stB = stA + HTILE * 2;

        #pragma unroll
        for (int ks = 0; ks < 4; ks++) {
            unsigned afr[4][4];
            #pragma unroll
            for (int mt = 0; mt < 4; mt++)
                ldsm_x4(afr[mt][0], afr[mt][1], afr[mt][2], afr[mt][3],
                        stA + aLdsmBase +
                        (unsigned)(mt * 16 * HSTRIDE * 2 + ks * 32));
            #pragma unroll
            for (int p = 0; p < 2; p++) {
                unsigned b00, b01, b10, b11;
                ldsm_x4(b00, b01, b10, b11,
                        stB + bPairBase +
                        (unsigned)(p * 16 * HSTRIDE * 2 + ks * 32));
                #pragma unroll
                for (int mt = 0; mt < 4; mt++) {
                    mma_f16(acc[mt * 4 + 2 * p], afr[mt][0], afr[mt][1],
                            afr[mt][2], afr[mt][3], b00, b01);
                    mma_f16(acc[mt * 4 + 2 * p + 1], afr[mt][0], afr[mt][1],
                            afr[mt][2], afr[mt][3], b10, b11);
                }
            }
        }
    }

    #pragma unroll
    for (int mt = 0; mt < 4; mt++) {
        #pragma unroll
        for (int nt = 0; nt < 4; nt++) {
            int row  = mBase + warpM + mt * 16 + gid;
            int coln = nBase + warpN + nt * 8 + 2 * tig;
            float b0 = bias[coln], b1 = bias[coln + 1];
            float* acc4 = acc[mt * 4 + nt];
            float v00 = acc4[0] + b0, v01 = acc4[1] + b1;
            float v10 = acc4[2] + b0, v11 = acc4[3] + b1;
            if (MODE == 1) {
                float s = (coln < DMODEL) ? 0.125f : 1.0f;
                __half2 h0 = __floats2half2_rn(v00 * s, v01 * s);
                __half2 h1 = __floats2half2_rn(v10 * s, v11 * s);
                *(__half2*)(Ch + (size_t)row * N_ + coln)       = h0;
                *(__half2*)(Ch + (size_t)(row + 8) * N_ + coln) = h1;
            } else {
                float2 w0 = {v00, v01}, w1 = {v10, v11};
                *(float2*)(C + (size_t)row * N_ + coln)       = w0;
                *(float2*)(C + (size_t)(row + 8) * N_ + coln) = w1;
            }
        }
    }
}

// ---------------------------------------------------------------------------
// Full fp16 flash attention. Q A-fragments are loop-invariant -> loaded ONCE
// from global into registers (no Q smem, no per-tile Q ldmatrix).
// K/V fp16 smem double-buffered, zero-shuffle P repack, 2 CTAs/SM.
// ---------------------------------------------------------------------------
#define KLDH 72
#define VLDH 72
#define K_BYTES (64 * KLDH * 2)
#define V_BYTES (64 * VLDH * 2)

__global__ __launch_bounds__(256, 2)
void flash_attn_tc(const __half* __restrict__ qkvh, __half* __restrict__ outh,
                   const int* __restrict__ causal_flag)
{
    extern __shared__ float sm[];
    const unsigned int smAddr = (unsigned int)__cvta_generic_to_shared(sm);
    const unsigned int kAddr0 = smAddr;
    const unsigned int vAddr0 = smAddr + 2 * K_BYTES;

    const int tid  = threadIdx.x;
    const int warp = tid >> 5;
    const int lane = tid & 31;
    const int gid  = lane >> 2;
    const int tig  = lane & 3;
    const int qBase = blockIdx.x * 128;
    const int h = blockIdx.y;
    const int b = blockIdx.z;
    const bool causal = (*causal_flag != 0);

    const int rowStride = 3 * DMODEL;
    const __half* qp = qkvh + (size_t)b * S_LEN * rowStride + h * HD;
    const __half* kp = qp + DMODEL;
    const __half* vp = qp + 2 * DMODEL;

    const int lg = lane >> 3;
    const int lr = lane & 7;
    const unsigned kPairBase =
        (unsigned)(((lg >> 1) * 8 + lr) * (KLDH * 2) + (lg & 1) * 16);
    const unsigned vLdsmBase =
        (unsigned)(((lg & 1) * 8 + lr) * (VLDH * 2) + (lg >> 1) * 16);

    const int row0g = qBase + warp * 16 + gid;

    // ---- Q A-fragments: loop-invariant, load once from global ----
    // m16k16 A-frag: a0=(gid, k+2tig), a1=(gid+8, ..), a2=(gid, k+8+2tig), a3=(gid+8, ..)
    unsigned qf[4][4];
    {
        const __half* q0 = qp + (size_t)row0g * rowStride;
        const __half* q1 = qp + (size_t)(row0g + 8) * rowStride;
        #pragma unroll
        for (int ks = 0; ks < 4; ks++) {
            int c = ks * 16 + tig * 2;
            qf[ks][0] = *(const unsigned*)(q0 + c);
            qf[ks][1] = *(const unsigned*)(q1 + c);
            qf[ks][2] = *(const unsigned*)(q0 + c + 8);
            qf[ks][3] = *(const unsigned*)(q1 + c + 8);
        }
    }

    int kn[2], kc[2];
    #pragma unroll
    for (int i = 0; i < 2; i++) {
        int s4 = tid + i * 256;
        kn[i] = s4 >> 3;
        kc[i] = (s4 & 7) * 8;
    }
    auto issue_kv = [&](int buf, int kBase) {
        unsigned int kB = kAddr0 + buf * K_BYTES;
        unsigned int vB = vAddr0 + buf * V_BYTES;
        #pragma unroll
        for (int i = 0; i < 2; i++) {
            size_t g = (size_t)(kBase + kn[i]) * rowStride + kc[i];
            cp_async16(kB + (kn[i] * KLDH + kc[i]) * 2, kp + g);
            cp_async16(vB + (kn[i] * VLDH + kc[i]) * 2, vp + g);
        }
    };

    int nTiles = S_LEN / 64;
    if (causal) nTiles = (qBase + 128) / 64;

    issue_kv(0, 0);
    cp_commit();

    float of[8][4];
    #pragma unroll
    for (int i = 0; i < 8; i++)
        #pragma unroll
        for (int j = 0; j < 4; j++) of[i][j] = 0.0f;
    float mrow0 = -1e30f, mrow1 = -1e30f, lrow0 = 0.0f, lrow1 = 0.0f;

    for (int t = 0; t < nTiles; t++) {
        const int kBase = t * 64;
        const int buf   = t & 1;

        cp_wait<0>();
        __syncthreads();
        if (t + 1 < nTiles) {
            issue_kv(1 - buf, kBase + 64);
            cp_commit();
        }

        const unsigned kStage = kAddr0 + buf * K_BYTES;
        const unsigned vStage = vAddr0 + buf * V_BYTES;

        // ---- Phase A: S = (Q/8) K^T ----
        float sc[8][4];
        #pragma unroll
        for (int i = 0; i < 8; i++)
            #pragma unroll
            for (int j = 0; j < 4; j++) sc[i][j] = 0.0f;

        #pragma unroll
        for (int ks = 0; ks < 4; ks++) {
            #pragma unroll
            for (int p = 0; p < 4; p++) {
                unsigned b00, b01, b10, b11;
                ldsm_x4(b00, b01, b10, b11,
                        kStage + kPairBase +
                        (unsigned)(p * 16 * (KLDH * 2) + ks * 32));
                mma_f16(sc[2 * p],     qf[ks][0], qf[ks][1], qf[ks][2], qf[ks][3],
                        b00, b01);
                mma_f16(sc[2 * p + 1], qf[ks][0], qf[ks][1], qf[ks][2], qf[ks][3],
                        b10, b11);
            }
        }

        // ---- online softmax ----
        float ml0 = -1e30f, ml1 = -1e30f;
        #pragma unroll
        for (int nt = 0; nt < 8; nt++) {
            int coln = kBase + nt * 8 + 2 * tig;
            #pragma unroll
            for (int cc = 0; cc < 4; cc++) {
                float v = sc[nt][cc];
                if (causal) {
                    int col = coln + (cc & 1);
                    int row = (cc < 2) ? row0g : (row0g + 8);
                    if (col > row) v = -1e30f;
                }
                sc[nt][cc] = v;
                if (cc < 2) ml0 = fmaxf(ml0, v);
                else        ml1 = fmaxf(ml1, v);
            }
        }
        #pragma unroll
        for (int off = 1; off < 4; off <<= 1) {
            ml0 = fmaxf(ml0, __shfl_xor_sync(0xffffffffu, ml0, off));
            ml1 = fmaxf(ml1, __shfl_xor_sync(0xffffffffu, ml1, off));
        }
        float mn0 = fmaxf(mrow0, ml0), mn1 = fmaxf(mrow1, ml1);
        float al0 = __expf(mrow0 - mn0), al1 = __expf(mrow1 - mn1);
        mrow0 = mn0; mrow1 = mn1;

        float rs0 = 0.0f, rs1 = 0.0f;
        #pragma unroll
        for (int nt = 0; nt < 8; nt++) {
            float p0 = __expf(sc[nt][0] - mn0);
            float p1 = __expf(sc[nt][1] - mn0);
            float p2 = __expf(sc[nt][2] - mn1);
            float p3 = __expf(sc[nt][3] - mn1);
            sc[nt][0] = p0; sc[nt][1] = p1; sc[nt][2] = p2; sc[nt][3] = p3;
            rs0 += p0 + p1; rs1 += p2 + p3;
        }
        #pragma unroll
        for (int off = 1; off < 4; off <<= 1) {
            rs0 += __shfl_xor_sync(0xffffffffu, rs0, off);
            rs1 += __shfl_xor_sync(0xffffffffu, rs1, off);
        }
        lrow0 = lrow0 * al0 + rs0;
        lrow1 = lrow1 * al1 + rs1;
        #pragma unroll
        for (int dt = 0; dt < 8; dt++) {
            of[dt][0] *= al0; of[dt][1] *= al0;
            of[dt][2] *= al1; of[dt][3] *= al1;
        }

        // ---- Phase B: O += P V (zero-shuffle P repack) ----
        #pragma unroll
        for (int kt = 0; kt < 4; kt++) {
            unsigned a0 = packh2(sc[2 * kt][0],     sc[2 * kt][1]);
            unsigned a1 = packh2(sc[2 * kt][2],     sc[2 * kt][3]);
            unsigned a2 = packh2(sc[2 * kt + 1][0], sc[2 * kt + 1][1]);
            unsigned a3 = packh2(sc[2 * kt + 1][2], sc[2 * kt + 1][3]);
            #pragma unroll
            for (int dp = 0; dp < 4; dp++) {
                unsigned b00, b01, b10, b11;
                ldsm_x4t(b00, b01, b10, b11,
                         vStage + vLdsmBase +
                         (unsigned)(kt * 16 * (VLDH * 2) + dp * 32));
                mma_f16(of[2 * dp],     a0, a1, a2, a3, b00, b01);
                mma_f16(of[2 * dp + 1], a0, a1, a2, a3, b10, b11);
            }
        }
    }

    // Epilogue: normalize, emit fp16 for gemm2
    float inv0 = 1.0f / lrow0, inv1 = 1.0f / lrow1;
    __half* op = outh + (size_t)b * S_LEN * DMODEL + h * HD;
    #pragma unroll
    for (int dt = 0; dt < 8; dt++) {
        int col = dt * 8 + 2 * tig;
        __half2 h0 = __floats2half2_rn(of[dt][0] * inv0, of[dt][1] * inv0);
        __half2 h1 = __floats2half2_rn(of[dt][2] * inv1, of[dt][3] * inv1);
        *(__half2*)(op + (size_t)row0g * DMODEL + col)       = h0;
        *(__half2*)(op + (size_t)(row0g + 8) * DMODEL + col) = h1;
    }
}

// ---------------------------------------------------------------------------
extern "C" void kernel_launch(void* const* d_in, const int* in_sizes, int n_in,
                              void* d_out, int out_size)
{
    (void)in_sizes; (void)n_in; (void)out_size;
    const float* features = (const float*)d_in[0];
    const float* qkv_w    = (const float*)d_in[1];
    const float* qkv_b    = (const float*)d_in[2];
    const float* out_w    = (const float*)d_in[3];
    const float* out_b    = (const float*)d_in[4];
    const int*   causal   = (const int*)d_in[5];
    float* out = (float*)d_out;

    __half* fh    = nullptr;
    __half* wh    = nullptr;
    __half* qkvh  = nullptr;
    __half* atth  = nullptr;
    cudaGetSymbolAddress((void**)&fh,   g_fh);
    cudaGetSymbolAddress((void**)&wh,   g_wh);
    cudaGetSymbolAddress((void**)&qkvh, g_qkvh);
    cudaGetSymbolAddress((void**)&atth, g_atth);

    const int SMEM_GEMM  = GSTAGES * HSTG_BYTES;            // 110592
    const int SMEM_FLASH = 2 * K_BYTES + 2 * V_BYTES;       // 36864

    cudaFuncSetAttribute(gemm_f16<3 * DMODEL, DMODEL, 1>,
                         cudaFuncAttributeMaxDynamicSharedMemorySize, SMEM_GEMM);
    cudaFuncSetAttribute(gemm_f16<DMODEL, DMODEL, 0>,
                         cudaFuncAttributeMaxDynamicSharedMemorySize, SMEM_GEMM);
    cudaFuncSetAttribute(flash_attn_tc,
                         cudaFuncAttributeMaxDynamicSharedMemorySize, SMEM_FLASH);

    // 0) fp32 -> fp16 conversion of all inputs
    {
        int total4 = NF4 + NW14 + NW24;
        to_half_kernel<<<(total4 + 255) / 256, 256>>>(
            (const float4*)features, (const float4*)qkv_w, (const float4*)out_w,
            fh, wh, wh + 3 * DMODEL * DMODEL);
    }

    // 1) QKV projection (fp16 MMA) -> fp16 QKV, Q pre-scaled by 1/8
    gemm_f16<3 * DMODEL, DMODEL, 1>
        <<<dim3(3 * DMODEL / 128, BATCH * S_LEN / 128), 256, SMEM_GEMM>>>(
            fh, wh, qkv_b, nullptr, qkvh);

    // 2) Attention (fp16 MMA, fp32 accumulate) -> fp16 output
    flash_attn_tc<<<dim3(S_LEN / 128, NH, BATCH), 256, SMEM_FLASH>>>(
        qkvh, atth, causal);

    // 3) Output projection (fp16 MMA, exact fp32 output)
    gemm_f16<DMODEL, DMODEL, 0>
        <<<dim3(DMODEL / 128, BATCH * S_LEN / 128), 256, SMEM_GEMM>>>(
            atth, wh + 3 * DMODEL * DMODEL, out_b, out, nullptr);
}